// round 5
// baseline (speedup 1.0000x reference)
#include <cuda_runtime.h>
#include <cuda_bf16.h>
#include <math.h>
#include <stdint.h>

// ============================================================================
// FlashAttention-v2 style causal MHA via mma.sync bf16 hi/lo split, sm_103.
// Register-resident P (S C-frags == PV A-frags), 2 CTAs/SM.
// q,k,v: [B,S,E] fp32, E=H*D, D=64. out: [B,S,E]. attn: [B,H,S,S].
// ============================================================================

namespace {
constexpr int kS = 2048, kE = 1024;
constexpr int NQT = 16;                          // 128-row q tiles
constexpr long long OUT_ELEMS  = 4194304LL;
constexpr long long ATTN_ELEMS = 134217728LL;

constexpr int QSTR = 72;                         // bf16 elems per row (144B)
constexpr int OFF_QH = 0;                        // Q hi [128][64]
constexpr int OFF_QL = OFF_QH + 128 * QSTR * 2;  // 18432
constexpr int OFF_KH = OFF_QL + 128 * QSTR * 2;  // 36864  K [64][64]
constexpr int OFF_KL = OFF_KH + 64 * QSTR * 2;   // 46080
constexpr int OFF_VH = OFF_KL + 64 * QSTR * 2;   // 55296  Vt [64 d][64 key]
constexpr int OFF_VL = OFF_VH + 64 * QSTR * 2;   // 64512
constexpr int OFF_L  = OFF_VL + 64 * QSTR * 2;   // 73728
constexpr int SMEM_BYTES = OFF_L + 128 * 4;      // 74240
}  // namespace

__device__ __forceinline__ uint32_t smem_u32(const void* p) {
    uint32_t a;
    asm("{ .reg .u64 t; cvta.to.shared.u64 t, %1; cvt.u32.u64 %0, t; }" : "=r"(a) : "l"(p));
    return a;
}
__device__ __forceinline__ void ldsm4(uint32_t r[4], uint32_t addr) {
    asm volatile("ldmatrix.sync.aligned.m8n8.x4.shared.b16 {%0,%1,%2,%3}, [%4];"
                 : "=r"(r[0]), "=r"(r[1]), "=r"(r[2]), "=r"(r[3]) : "r"(addr));
}
__device__ __forceinline__ void mma16816(float c[4], const uint32_t a[4],
                                         uint32_t b0, uint32_t b1) {
    asm("mma.sync.aligned.m16n8k16.row.col.f32.bf16.bf16.f32 "
        "{%0,%1,%2,%3}, {%4,%5,%6,%7}, {%8,%9}, {%0,%1,%2,%3};"
        : "+f"(c[0]), "+f"(c[1]), "+f"(c[2]), "+f"(c[3])
        : "r"(a[0]), "r"(a[1]), "r"(a[2]), "r"(a[3]), "r"(b0), "r"(b1));
}
__device__ __forceinline__ float bfr(float x) {
    return __bfloat162float(__float2bfloat16(x));
}
__device__ __forceinline__ uint32_t packbf(float lo_c, float hi_c) {  // {low half, high half}
    uint32_t r;
    asm("cvt.rn.bf16x2.f32 %0, %1, %2;" : "=r"(r) : "f"(hi_c), "f"(lo_c));
    return r;
}

// S[j][4] (j = 8-col n-block 0..7) += Q(16 rows of this warp) * K_tile(64x64)^T,
// 3-product bf16 hi/lo split. arow/akh/brow/bkh are lane-derived ldmatrix params.
__device__ __forceinline__ void s_gemm(float (&S)[8][4], uint32_t sb, int wr,
                                       int arow, int akh, int brow, int bkh) {
    #pragma unroll
    for (int kb = 0; kb < 4; kb++) {
        uint32_t ah[4], al[4];
        uint32_t aoff = (uint32_t)(((wr + arow) * QSTR + kb * 16 + akh * 8) * 2);
        ldsm4(ah, sb + OFF_QH + aoff);
        ldsm4(al, sb + OFF_QL + aoff);
        #pragma unroll
        for (int jp = 0; jp < 4; jp++) {
            uint32_t boff = (uint32_t)(((jp * 16 + brow) * QSTR + kb * 16 + bkh * 8) * 2);
            uint32_t bh[4], bl[4];
            ldsm4(bh, sb + OFF_KH + boff);
            ldsm4(bl, sb + OFF_KL + boff);
            mma16816(S[2 * jp + 0], ah, bh[0], bh[1]);
            mma16816(S[2 * jp + 0], al, bh[0], bh[1]);
            mma16816(S[2 * jp + 0], ah, bl[0], bl[1]);
            mma16816(S[2 * jp + 1], ah, bh[2], bh[3]);
            mma16816(S[2 * jp + 1], al, bh[2], bh[3]);
            mma16816(S[2 * jp + 1], ah, bl[2], bl[3]);
        }
    }
}

__global__ __launch_bounds__(256, 2)
void attn_flash_kernel(const float* __restrict__ q, const float* __restrict__ k,
                       const float* __restrict__ v, float* __restrict__ out,
                       float* __restrict__ attn) {
    extern __shared__ char smc[];
    const uint32_t sb = smem_u32(smc);
    float* lsm = (float*)(smc + OFF_L);

    const int tid = threadIdx.x;
    const int lane = tid & 31;
    const int wid = tid >> 5;                 // 0..7, owns q rows wid*16..+15
    const int g = lane >> 2, t = lane & 3;
    const int wr = wid * 16;

    const int arow = lane & 15, akh = lane >> 4;
    const int brow = ((lane >> 4) & 1) * 8 + (lane & 7), bkh = (lane >> 3) & 1;

    const int qt = (NQT - 1) - blockIdx.x;    // heavy tiles first
    const int bh = blockIdx.y;
    const int b = bh >> 4, h = bh & 15;

    const float* qb = q + (long long)b * kS * kE + h * 64;
    const float* kb = k + (long long)b * kS * kE + h * 64;
    const float* vb = v + (long long)b * kS * kE + h * 64;
    float* ob = out + (long long)b * kS * kE + h * 64;
    float* ab = attn ? attn + (long long)bh * kS * kS : nullptr;

    const int nkt = 2 * qt + 2;               // 64-key tiles
    const int qrow_g = qt * 128 + wr + g;     // rows for c0/c1; +8 for c2/c3

    // ---- load Q (x 1/8, hi/lo bf16 split) ----
    #pragma unroll
    for (int i = 0; i < 8; i++) {
        int e4 = tid + i * 256;
        int r = e4 >> 4, d4 = (e4 & 15) << 2;
        float4 x = *(const float4*)&qb[(long long)(qt * 128 + r) * kE + d4];
        x.x *= 0.125f; x.y *= 0.125f; x.z *= 0.125f; x.w *= 0.125f;
        float h0 = bfr(x.x), h1 = bfr(x.y), h2 = bfr(x.z), h3 = bfr(x.w);
        uint32_t off = (uint32_t)((r * QSTR + d4) * 2);
        *(uint32_t*)(smc + OFF_QH + off)     = packbf(h0, h1);
        *(uint32_t*)(smc + OFF_QH + off + 4) = packbf(h2, h3);
        *(uint32_t*)(smc + OFF_QL + off)     = packbf(x.x - h0, x.y - h1);
        *(uint32_t*)(smc + OFF_QL + off + 4) = packbf(x.z - h2, x.w - h3);
    }

    float O[8][4];
    #pragma unroll
    for (int nb = 0; nb < 8; nb++)
        #pragma unroll
        for (int c = 0; c < 4; c++) O[nb][c] = 0.0f;
    float lp0 = 0.0f, lp1 = 0.0f;

    // =====================================================================
    // PASS 1: online (max-free) softmax accumulation + O = P*V
    // =====================================================================
    for (int kt = 0; kt < nkt; kt++) {
        // store K tile [64][64] hi/lo
        #pragma unroll
        for (int i = 0; i < 4; i++) {
            int e4 = tid + i * 256;
            int r = e4 >> 4, d4 = (e4 & 15) << 2;
            float4 x = *(const float4*)&kb[(long long)(kt * 64 + r) * kE + d4];
            float h0 = bfr(x.x), h1 = bfr(x.y), h2 = bfr(x.z), h3 = bfr(x.w);
            uint32_t off = (uint32_t)((r * QSTR + d4) * 2);
            *(uint32_t*)(smc + OFF_KH + off)     = packbf(h0, h1);
            *(uint32_t*)(smc + OFF_KH + off + 4) = packbf(h2, h3);
            *(uint32_t*)(smc + OFF_KL + off)     = packbf(x.x - h0, x.y - h1);
            *(uint32_t*)(smc + OFF_KL + off + 4) = packbf(x.z - h2, x.w - h3);
        }
        // store Vt [d][key] hi/lo
        #pragma unroll
        for (int i = 0; i < 4; i++) {
            int idx = tid + i * 256;
            int key = idx >> 4, dg = idx & 15;
            float4 x = *(const float4*)&vb[(long long)(kt * 64 + key) * kE + dg * 4];
            #pragma unroll
            for (int j = 0; j < 4; j++) {
                float val = (&x.x)[j];
                float hi = bfr(val);
                int d = dg * 4 + j;
                *(__nv_bfloat16*)(smc + OFF_VH + (d * QSTR + key) * 2) = __float2bfloat16(hi);
                *(__nv_bfloat16*)(smc + OFF_VL + (d * QSTR + key) * 2) = __float2bfloat16(val - hi);
            }
        }
        __syncthreads();

        // ---- S = Q*K^T ----
        float S[8][4];
        #pragma unroll
        for (int j = 0; j < 8; j++)
            #pragma unroll
            for (int c = 0; c < 4; c++) S[j][c] = 0.0f;
        s_gemm(S, sb, wr, arow, akh, brow, bkh);

        // ---- epilogue: exp, l-partials, convert to PV A-fragments ----
        const bool need_mask = (kt * 64 + 63 > qt * 128 + wr);
        uint32_t ph[8][2], pl[8][2];
        #pragma unroll
        for (int j = 0; j < 8; j++) {
            const int c0 = kt * 64 + j * 8 + 2 * t;
            float e0 = __expf(S[j][0]), e1 = __expf(S[j][1]);
            float e2 = __expf(S[j][2]), e3 = __expf(S[j][3]);
            if (need_mask) {
                if (c0     > qrow_g)     e0 = 0.0f;
                if (c0 + 1 > qrow_g)     e1 = 0.0f;
                if (c0     > qrow_g + 8) e2 = 0.0f;
                if (c0 + 1 > qrow_g + 8) e3 = 0.0f;
            }
            lp0 += e0 + e1;
            lp1 += e2 + e3;
            float h0 = bfr(e0), h1 = bfr(e1), h2 = bfr(e2), h3 = bfr(e3);
            ph[j][0] = packbf(h0, h1);
            ph[j][1] = packbf(h2, h3);
            pl[j][0] = packbf(e0 - h0, e1 - h1);
            pl[j][1] = packbf(e2 - h2, e3 - h3);
        }

        // ---- O += P*V (A from registers, B = Vt fragments) ----
        #pragma unroll
        for (int kb4 = 0; kb4 < 4; kb4++) {
            uint32_t Ah[4] = {ph[2 * kb4][0], ph[2 * kb4][1],
                              ph[2 * kb4 + 1][0], ph[2 * kb4 + 1][1]};
            uint32_t Al[4] = {pl[2 * kb4][0], pl[2 * kb4][1],
                              pl[2 * kb4 + 1][0], pl[2 * kb4 + 1][1]};
            #pragma unroll
            for (int np = 0; np < 4; np++) {
                uint32_t boff = (uint32_t)(((np * 16 + brow) * QSTR + kb4 * 16 + bkh * 8) * 2);
                uint32_t vh[4], vl[4];
                ldsm4(vh, sb + OFF_VH + boff);
                ldsm4(vl, sb + OFF_VL + boff);
                mma16816(O[2 * np + 0], Ah, vh[0], vh[1]);
                mma16816(O[2 * np + 0], Al, vh[0], vh[1]);
                mma16816(O[2 * np + 0], Ah, vl[0], vl[1]);
                mma16816(O[2 * np + 1], Ah, vh[2], vh[3]);
                mma16816(O[2 * np + 1], Al, vh[2], vh[3]);
                mma16816(O[2 * np + 1], Ah, vl[2], vl[3]);
            }
        }
        __syncthreads();
    }

    // ---- reduce l across quad lanes; rows are warp-private ----
    lp0 += __shfl_xor_sync(0xffffffffu, lp0, 1);
    lp0 += __shfl_xor_sync(0xffffffffu, lp0, 2);
    lp1 += __shfl_xor_sync(0xffffffffu, lp1, 1);
    lp1 += __shfl_xor_sync(0xffffffffu, lp1, 2);
    if (t == 0) {
        lsm[wr + g] = lp0;
        lsm[wr + 8 + g] = lp1;
    }
    __syncthreads();
    const float ril = 1.0f / lsm[wr + g];
    const float rih = 1.0f / lsm[wr + 8 + g];

    // ---- write O (normalized) ----
    #pragma unroll
    for (int nb = 0; nb < 8; nb++) {
        const int c0 = nb * 8 + 2 * t;
        *(float2*)&ob[(long long)qrow_g * kE + c0] =
            make_float2(O[nb][0] * ril, O[nb][1] * ril);
        *(float2*)&ob[(long long)(qrow_g + 8) * kE + c0] =
            make_float2(O[nb][2] * rih, O[nb][3] * rih);
    }

    // =====================================================================
    // PASS 2: recompute S, write normalized attn
    // =====================================================================
    if (ab) {
        for (int kt = 0; kt < nkt; kt++) {
            #pragma unroll
            for (int i = 0; i < 4; i++) {
                int e4 = tid + i * 256;
                int r = e4 >> 4, d4 = (e4 & 15) << 2;
                float4 x = *(const float4*)&kb[(long long)(kt * 64 + r) * kE + d4];
                float h0 = bfr(x.x), h1 = bfr(x.y), h2 = bfr(x.z), h3 = bfr(x.w);
                uint32_t off = (uint32_t)((r * QSTR + d4) * 2);
                *(uint32_t*)(smc + OFF_KH + off)     = packbf(h0, h1);
                *(uint32_t*)(smc + OFF_KH + off + 4) = packbf(h2, h3);
                *(uint32_t*)(smc + OFF_KL + off)     = packbf(x.x - h0, x.y - h1);
                *(uint32_t*)(smc + OFF_KL + off + 4) = packbf(x.z - h2, x.w - h3);
            }
            __syncthreads();

            float S[8][4];
            #pragma unroll
            for (int j = 0; j < 8; j++)
                #pragma unroll
                for (int c = 0; c < 4; c++) S[j][c] = 0.0f;
            s_gemm(S, sb, wr, arow, akh, brow, bkh);

            const bool need_mask = (kt * 64 + 63 > qt * 128 + wr);
            #pragma unroll
            for (int j = 0; j < 8; j++) {
                const int c0 = kt * 64 + j * 8 + 2 * t;
                float p0 = __expf(S[j][0]) * ril, p1 = __expf(S[j][1]) * ril;
                float p2 = __expf(S[j][2]) * rih, p3 = __expf(S[j][3]) * rih;
                if (need_mask) {
                    if (c0     > qrow_g)     p0 = 0.0f;
                    if (c0 + 1 > qrow_g)     p1 = 0.0f;
                    if (c0     > qrow_g + 8) p2 = 0.0f;
                    if (c0 + 1 > qrow_g + 8) p3 = 0.0f;
                }
                *(float2*)&ab[(long long)qrow_g * kS + c0]       = make_float2(p0, p1);
                *(float2*)&ab[(long long)(qrow_g + 8) * kS + c0] = make_float2(p2, p3);
            }
            __syncthreads();
        }

        // ---- zero-fill masked columns [nkt*64, 2048) ----
        const int cz0 = nkt * 64;
        const int w4 = (kS - cz0) >> 2;
        if (w4 > 0) {
            const float4 z4 = make_float4(0.f, 0.f, 0.f, 0.f);
            for (int i = tid; i < 128 * w4; i += 256) {
                int r = i / w4;
                int c = (i - r * w4) * 4 + cz0;
                *(float4*)&ab[(long long)(qt * 128 + r) * kS + c] = z4;
            }
        }
    }
}

extern "C" void kernel_launch(void* const* d_in, const int* in_sizes, int n_in,
                              void* d_out, int out_size) {
    const float* q = (const float*)d_in[0];
    const float* k = (const float*)d_in[1];
    const float* v = (const float*)d_in[2];
    float* out = (float*)d_out;

    float* attn = nullptr;
    if ((long long)out_size >= OUT_ELEMS + ATTN_ELEMS) attn = out + OUT_ELEMS;

    cudaFuncSetAttribute(attn_flash_kernel,
                         cudaFuncAttributeMaxDynamicSharedMemorySize, SMEM_BYTES);

    dim3 grid(NQT, 32);
    attn_flash_kernel<<<grid, 256, SMEM_BYTES>>>(q, k, v, out, attn);
}

// round 6
// speedup vs baseline: 1.0451x; 1.0451x over previous
#include <cuda_runtime.h>
#include <cuda_bf16.h>
#include <math.h>
#include <stdint.h>

// ============================================================================
// Causal MHA, sm_103. Kernel 1: FA2-style single pass (mma.sync bf16 hi/lo),
// writes out + UNNORMALIZED exp(S) to attn + per-row 1/l to global.
// Kernel 2: streaming scale of attn's causal region by 1/l.
// q,k,v: [B,S,E] fp32, E=H*D, D=64. out: [B,S,E]. attn: [B,H,S,S].
// ============================================================================

namespace {
constexpr int kS = 2048, kE = 1024;
constexpr int NQT = 16;                          // 128-row q tiles
constexpr long long OUT_ELEMS  = 4194304LL;
constexpr long long ATTN_ELEMS = 134217728LL;

constexpr int QSTR = 72;                         // bf16 elems per row (144B)
constexpr int OFF_QH = 0;                        // Q hi [128][64]
constexpr int OFF_QL = OFF_QH + 128 * QSTR * 2;  // 18432
constexpr int OFF_KH = OFF_QL + 128 * QSTR * 2;  // 36864  K [64][64]
constexpr int OFF_KL = OFF_KH + 64 * QSTR * 2;   // 46080
constexpr int OFF_VH = OFF_KL + 64 * QSTR * 2;   // 55296  Vt [64 d][64 key]
constexpr int OFF_VL = OFF_VH + 64 * QSTR * 2;   // 64512
constexpr int OFF_L  = OFF_VL + 64 * QSTR * 2;   // 73728
constexpr int SMEM_BYTES = OFF_L + 128 * 4;      // 74240
}  // namespace

__device__ float g_rinv[32 * 2048];              // per (bh,row) 1/l

__device__ __forceinline__ uint32_t smem_u32(const void* p) {
    uint32_t a;
    asm("{ .reg .u64 t; cvta.to.shared.u64 t, %1; cvt.u32.u64 %0, t; }" : "=r"(a) : "l"(p));
    return a;
}
__device__ __forceinline__ void ldsm4(uint32_t r[4], uint32_t addr) {
    asm volatile("ldmatrix.sync.aligned.m8n8.x4.shared.b16 {%0,%1,%2,%3}, [%4];"
                 : "=r"(r[0]), "=r"(r[1]), "=r"(r[2]), "=r"(r[3]) : "r"(addr));
}
__device__ __forceinline__ void mma16816(float c[4], const uint32_t a[4],
                                         uint32_t b0, uint32_t b1) {
    asm("mma.sync.aligned.m16n8k16.row.col.f32.bf16.bf16.f32 "
        "{%0,%1,%2,%3}, {%4,%5,%6,%7}, {%8,%9}, {%0,%1,%2,%3};"
        : "+f"(c[0]), "+f"(c[1]), "+f"(c[2]), "+f"(c[3])
        : "r"(a[0]), "r"(a[1]), "r"(a[2]), "r"(a[3]), "r"(b0), "r"(b1));
}
__device__ __forceinline__ float bfr(float x) {
    return __bfloat162float(__float2bfloat16(x));
}
__device__ __forceinline__ uint32_t packbf(float lo_c, float hi_c) {  // {low, high}
    uint32_t r;
    asm("cvt.rn.bf16x2.f32 %0, %1, %2;" : "=r"(r) : "f"(hi_c), "f"(lo_c));
    return r;
}

// S[j][4] += Q(16 rows of this warp) * K_tile(64x64)^T, 3-product bf16 split.
__device__ __forceinline__ void s_gemm(float (&S)[8][4], uint32_t sb, int wr,
                                       int arow, int akh, int brow, int bkh) {
    #pragma unroll
    for (int kb = 0; kb < 4; kb++) {
        uint32_t ah[4], al[4];
        uint32_t aoff = (uint32_t)(((wr + arow) * QSTR + kb * 16 + akh * 8) * 2);
        ldsm4(ah, sb + OFF_QH + aoff);
        ldsm4(al, sb + OFF_QL + aoff);
        #pragma unroll
        for (int jp = 0; jp < 4; jp++) {
            uint32_t boff = (uint32_t)(((jp * 16 + brow) * QSTR + kb * 16 + bkh * 8) * 2);
            uint32_t bh[4], bl[4];
            ldsm4(bh, sb + OFF_KH + boff);
            ldsm4(bl, sb + OFF_KL + boff);
            mma16816(S[2 * jp + 0], ah, bh[0], bh[1]);
            mma16816(S[2 * jp + 0], al, bh[0], bh[1]);
            mma16816(S[2 * jp + 0], ah, bl[0], bl[1]);
            mma16816(S[2 * jp + 1], ah, bh[2], bh[3]);
            mma16816(S[2 * jp + 1], al, bh[2], bh[3]);
            mma16816(S[2 * jp + 1], ah, bl[2], bl[3]);
        }
    }
}

// ============================================================================
// Kernel 1: attention compute; attn gets UNNORMALIZED exp(S)
// ============================================================================
__global__ __launch_bounds__(256, 2)
void attn_main_kernel(const float* __restrict__ q, const float* __restrict__ k,
                      const float* __restrict__ v, float* __restrict__ out,
                      float* __restrict__ attn) {
    extern __shared__ char smc[];
    const uint32_t sb = smem_u32(smc);
    float* lsm = (float*)(smc + OFF_L);

    const int tid = threadIdx.x;
    const int lane = tid & 31;
    const int wid = tid >> 5;                 // owns q rows wid*16..+15
    const int g = lane >> 2, t = lane & 3;
    const int wr = wid * 16;

    const int arow = lane & 15, akh = lane >> 4;
    const int brow = ((lane >> 4) & 1) * 8 + (lane & 7), bkh = (lane >> 3) & 1;

    const int qt = (NQT - 1) - blockIdx.x;    // heavy tiles first
    const int bh = blockIdx.y;
    const int b = bh >> 4, h = bh & 15;

    const float* qb = q + (long long)b * kS * kE + h * 64;
    const float* kb = k + (long long)b * kS * kE + h * 64;
    const float* vb = v + (long long)b * kS * kE + h * 64;
    float* ob = out + (long long)b * kS * kE + h * 64;
    float* ab = attn ? attn + (long long)bh * kS * kS : nullptr;

    const int nkt = 2 * qt + 2;               // 64-key tiles
    const int qrow_g = qt * 128 + wr + g;     // rows for c0/c1; +8 for c2/c3

    // ---- load Q (x 1/8, hi/lo bf16 split) ----
    #pragma unroll
    for (int i = 0; i < 8; i++) {
        int e4 = tid + i * 256;
        int r = e4 >> 4, d4 = (e4 & 15) << 2;
        float4 x = *(const float4*)&qb[(long long)(qt * 128 + r) * kE + d4];
        x.x *= 0.125f; x.y *= 0.125f; x.z *= 0.125f; x.w *= 0.125f;
        float h0 = bfr(x.x), h1 = bfr(x.y), h2 = bfr(x.z), h3 = bfr(x.w);
        uint32_t off = (uint32_t)((r * QSTR + d4) * 2);
        *(uint32_t*)(smc + OFF_QH + off)     = packbf(h0, h1);
        *(uint32_t*)(smc + OFF_QH + off + 4) = packbf(h2, h3);
        *(uint32_t*)(smc + OFF_QL + off)     = packbf(x.x - h0, x.y - h1);
        *(uint32_t*)(smc + OFF_QL + off + 4) = packbf(x.z - h2, x.w - h3);
    }

    float O[8][4];
    #pragma unroll
    for (int nb = 0; nb < 8; nb++)
        #pragma unroll
        for (int c = 0; c < 4; c++) O[nb][c] = 0.0f;
    float lp0 = 0.0f, lp1 = 0.0f;

    for (int kt = 0; kt < nkt; kt++) {
        // store K tile [64][64] hi/lo
        #pragma unroll
        for (int i = 0; i < 4; i++) {
            int e4 = tid + i * 256;
            int r = e4 >> 4, d4 = (e4 & 15) << 2;
            float4 x = *(const float4*)&kb[(long long)(kt * 64 + r) * kE + d4];
            float h0 = bfr(x.x), h1 = bfr(x.y), h2 = bfr(x.z), h3 = bfr(x.w);
            uint32_t off = (uint32_t)((r * QSTR + d4) * 2);
            *(uint32_t*)(smc + OFF_KH + off)     = packbf(h0, h1);
            *(uint32_t*)(smc + OFF_KH + off + 4) = packbf(h2, h3);
            *(uint32_t*)(smc + OFF_KL + off)     = packbf(x.x - h0, x.y - h1);
            *(uint32_t*)(smc + OFF_KL + off + 4) = packbf(x.z - h2, x.w - h3);
        }
        // store Vt [d][key] hi/lo
        #pragma unroll
        for (int i = 0; i < 4; i++) {
            int idx = tid + i * 256;
            int key = idx >> 4, dg = idx & 15;
            float4 x = *(const float4*)&vb[(long long)(kt * 64 + key) * kE + dg * 4];
            #pragma unroll
            for (int j = 0; j < 4; j++) {
                float val = (&x.x)[j];
                float hi = bfr(val);
                int d = dg * 4 + j;
                *(__nv_bfloat16*)(smc + OFF_VH + (d * QSTR + key) * 2) = __float2bfloat16(hi);
                *(__nv_bfloat16*)(smc + OFF_VL + (d * QSTR + key) * 2) = __float2bfloat16(val - hi);
            }
        }
        __syncthreads();

        // ---- S = Q*K^T ----
        float S[8][4];
        #pragma unroll
        for (int j = 0; j < 8; j++)
            #pragma unroll
            for (int c = 0; c < 4; c++) S[j][c] = 0.0f;
        s_gemm(S, sb, wr, arow, akh, brow, bkh);

        // ---- epilogue: exp, write unnormalized attn, l-partials, P frags ----
        const bool need_mask = (kt * 64 + 63 > qt * 128 + wr);
        uint32_t ph[8][2], pl[8][2];
        #pragma unroll
        for (int j = 0; j < 8; j++) {
            const int c0 = kt * 64 + j * 8 + 2 * t;
            float e0 = __expf(S[j][0]), e1 = __expf(S[j][1]);
            float e2 = __expf(S[j][2]), e3 = __expf(S[j][3]);
            if (need_mask) {
                if (c0     > qrow_g)     e0 = 0.0f;
                if (c0 + 1 > qrow_g)     e1 = 0.0f;
                if (c0     > qrow_g + 8) e2 = 0.0f;
                if (c0 + 1 > qrow_g + 8) e3 = 0.0f;
            }
            if (ab) {
                *(float2*)&ab[(long long)qrow_g * kS + c0]       = make_float2(e0, e1);
                *(float2*)&ab[(long long)(qrow_g + 8) * kS + c0] = make_float2(e2, e3);
            }
            lp0 += e0 + e1;
            lp1 += e2 + e3;
            float h0 = bfr(e0), h1 = bfr(e1), h2 = bfr(e2), h3 = bfr(e3);
            ph[j][0] = packbf(h0, h1);
            ph[j][1] = packbf(h2, h3);
            pl[j][0] = packbf(e0 - h0, e1 - h1);
            pl[j][1] = packbf(e2 - h2, e3 - h3);
        }

        // ---- O += P*V ----
        #pragma unroll
        for (int kb4 = 0; kb4 < 4; kb4++) {
            uint32_t Ah[4] = {ph[2 * kb4][0], ph[2 * kb4][1],
                              ph[2 * kb4 + 1][0], ph[2 * kb4 + 1][1]};
            uint32_t Al[4] = {pl[2 * kb4][0], pl[2 * kb4][1],
                              pl[2 * kb4 + 1][0], pl[2 * kb4 + 1][1]};
            #pragma unroll
            for (int np = 0; np < 4; np++) {
                uint32_t boff = (uint32_t)(((np * 16 + brow) * QSTR + kb4 * 16 + bkh * 8) * 2);
                uint32_t vh[4], vl[4];
                ldsm4(vh, sb + OFF_VH + boff);
                ldsm4(vl, sb + OFF_VL + boff);
                mma16816(O[2 * np + 0], Ah, vh[0], vh[1]);
                mma16816(O[2 * np + 0], Al, vh[0], vh[1]);
                mma16816(O[2 * np + 0], Ah, vl[0], vl[1]);
                mma16816(O[2 * np + 1], Ah, vh[2], vh[3]);
                mma16816(O[2 * np + 1], Al, vh[2], vh[3]);
                mma16816(O[2 * np + 1], Ah, vl[2], vl[3]);
            }
        }
        __syncthreads();
    }

    // ---- reduce l across quad lanes ----
    lp0 += __shfl_xor_sync(0xffffffffu, lp0, 1);
    lp0 += __shfl_xor_sync(0xffffffffu, lp0, 2);
    lp1 += __shfl_xor_sync(0xffffffffu, lp1, 1);
    lp1 += __shfl_xor_sync(0xffffffffu, lp1, 2);
    if (t == 0) {
        lsm[wr + g] = lp0;
        lsm[wr + 8 + g] = lp1;
    }
    __syncthreads();
    const float ril = 1.0f / lsm[wr + g];
    const float rih = 1.0f / lsm[wr + 8 + g];
    if (t == 0) {
        g_rinv[bh * kS + qrow_g] = ril;
        g_rinv[bh * kS + qrow_g + 8] = rih;
    }

    // ---- write O (normalized) ----
    #pragma unroll
    for (int nb = 0; nb < 8; nb++) {
        const int c0 = nb * 8 + 2 * t;
        *(float2*)&ob[(long long)qrow_g * kE + c0] =
            make_float2(O[nb][0] * ril, O[nb][1] * ril);
        *(float2*)&ob[(long long)(qrow_g + 8) * kE + c0] =
            make_float2(O[nb][2] * rih, O[nb][3] * rih);
    }

    // ---- zero-fill masked columns [nkt*64, 2048) ----
    if (ab) {
        const int cz0 = nkt * 64;
        const int w4 = (kS - cz0) >> 2;
        if (w4 > 0) {
            const float4 z4 = make_float4(0.f, 0.f, 0.f, 0.f);
            for (int i = tid; i < 128 * w4; i += 256) {
                int r = i / w4;
                int c = (i - r * w4) * 4 + cz0;
                *(float4*)&ab[(long long)(qt * 128 + r) * kS + c] = z4;
            }
        }
    }
}

// ============================================================================
// Kernel 2: attn[row, 0..r] *= rinv[row]   (streaming, DRAM-bound)
// ============================================================================
__global__ __launch_bounds__(256)
void attn_scale_kernel(float* __restrict__ attn) {
    const int rowg = blockIdx.x;              // bh*2048 + r
    const int r = rowg & (kS - 1);
    const float s = g_rinv[rowg];
    float4* p = (float4*)(attn + (long long)rowg * kS);
    const int n4 = (r + 4) >> 2;              // covers [0..r]; extra lanes hit zeros
    for (int i = threadIdx.x; i < n4; i += 256) {
        float4 x = p[i];
        x.x *= s; x.y *= s; x.z *= s; x.w *= s;
        p[i] = x;
    }
}

extern "C" void kernel_launch(void* const* d_in, const int* in_sizes, int n_in,
                              void* d_out, int out_size) {
    const float* q = (const float*)d_in[0];
    const float* k = (const float*)d_in[1];
    const float* v = (const float*)d_in[2];
    float* out = (float*)d_out;

    float* attn = nullptr;
    if ((long long)out_size >= OUT_ELEMS + ATTN_ELEMS) attn = out + OUT_ELEMS;

    cudaFuncSetAttribute(attn_main_kernel,
                         cudaFuncAttributeMaxDynamicSharedMemorySize, SMEM_BYTES);

    dim3 grid(NQT, 32);
    attn_main_kernel<<<grid, 256, SMEM_BYTES>>>(q, k, v, out, attn);
    if (attn) {
        attn_scale_kernel<<<32 * kS, 256>>>(attn);
    }
}

// round 7
// speedup vs baseline: 1.0561x; 1.0105x over previous
#include <cuda_runtime.h>
#include <cuda_bf16.h>
#include <math.h>
#include <stdint.h>

// ============================================================================
// Causal MHA, sm_103. Kernel 1: FA2-style single pass (mma.sync bf16 hi/lo),
// cp.async-pipelined K/V staging; writes out + UNNORMALIZED exp(S) to attn +
// per-row 1/l. Kernel 2: uniform-tile streaming scale of attn by 1/l.
// ============================================================================

namespace {
constexpr int kS = 2048, kE = 1024;
constexpr int NQT = 16;                          // 128-row q tiles
constexpr long long OUT_ELEMS  = 4194304LL;
constexpr long long ATTN_ELEMS = 134217728LL;

constexpr int QSTR = 72;                         // bf16 elems per row (144B)
constexpr int OFF_QH = 0;                        // Q hi [128][64]
constexpr int OFF_QL = OFF_QH + 128 * QSTR * 2;  // 18432
constexpr int OFF_KH = OFF_QL + 128 * QSTR * 2;  // 36864  K [64][64]
constexpr int OFF_KL = OFF_KH + 64 * QSTR * 2;   // 46080
constexpr int OFF_VH = OFF_KL + 64 * QSTR * 2;   // 55296  Vt [64 d][64 key]
constexpr int OFF_VL = OFF_VH + 64 * QSTR * 2;   // 64512
constexpr int OFF_L  = OFF_VL + 64 * QSTR * 2;   // 73728 (512B)
constexpr int OFF_RAWK = 74240;                  // raw K [64][64] f32 (16KB)
constexpr int OFF_RAWV = OFF_RAWK + 16384;       // raw V [64][64] f32 (16KB)
constexpr int SMEM_BYTES = OFF_RAWV + 16384;     // 107008
}  // namespace

__device__ float g_rinv[32 * 2048];              // per (bh,row) 1/l

__device__ __forceinline__ uint32_t smem_u32(const void* p) {
    uint32_t a;
    asm("{ .reg .u64 t; cvta.to.shared.u64 t, %1; cvt.u32.u64 %0, t; }" : "=r"(a) : "l"(p));
    return a;
}
__device__ __forceinline__ void ldsm4(uint32_t r[4], uint32_t addr) {
    asm volatile("ldmatrix.sync.aligned.m8n8.x4.shared.b16 {%0,%1,%2,%3}, [%4];"
                 : "=r"(r[0]), "=r"(r[1]), "=r"(r[2]), "=r"(r[3]) : "r"(addr));
}
__device__ __forceinline__ void mma16816(float c[4], const uint32_t a[4],
                                         uint32_t b0, uint32_t b1) {
    asm("mma.sync.aligned.m16n8k16.row.col.f32.bf16.bf16.f32 "
        "{%0,%1,%2,%3}, {%4,%5,%6,%7}, {%8,%9}, {%0,%1,%2,%3};"
        : "+f"(c[0]), "+f"(c[1]), "+f"(c[2]), "+f"(c[3])
        : "r"(a[0]), "r"(a[1]), "r"(a[2]), "r"(a[3]), "r"(b0), "r"(b1));
}
__device__ __forceinline__ float bfr(float x) {
    return __bfloat162float(__float2bfloat16(x));
}
__device__ __forceinline__ uint32_t packbf(float lo_c, float hi_c) {  // {low, high}
    uint32_t r;
    asm("cvt.rn.bf16x2.f32 %0, %1, %2;" : "=r"(r) : "f"(hi_c), "f"(lo_c));
    return r;
}
__device__ __forceinline__ void cp16(uint32_t smaddr, const void* gaddr) {
    asm volatile("cp.async.cg.shared.global [%0], [%1], 16;"
                 :: "r"(smaddr), "l"(gaddr) : "memory");
}
#define CP_COMMIT() asm volatile("cp.async.commit_group;" ::: "memory")
#define CP_WAIT0()  asm volatile("cp.async.wait_group 0;" ::: "memory")

// S[j][4] += Q(16 rows of this warp) * K_tile(64x64)^T, 3-product bf16 split.
__device__ __forceinline__ void s_gemm(float (&S)[8][4], uint32_t sb, int wr,
                                       int arow, int akh, int brow, int bkh) {
    #pragma unroll
    for (int kb = 0; kb < 4; kb++) {
        uint32_t ah[4], al[4];
        uint32_t aoff = (uint32_t)(((wr + arow) * QSTR + kb * 16 + akh * 8) * 2);
        ldsm4(ah, sb + OFF_QH + aoff);
        ldsm4(al, sb + OFF_QL + aoff);
        #pragma unroll
        for (int jp = 0; jp < 4; jp++) {
            uint32_t boff = (uint32_t)(((jp * 16 + brow) * QSTR + kb * 16 + bkh * 8) * 2);
            uint32_t bh[4], bl[4];
            ldsm4(bh, sb + OFF_KH + boff);
            ldsm4(bl, sb + OFF_KL + boff);
            mma16816(S[2 * jp + 0], ah, bh[0], bh[1]);
            mma16816(S[2 * jp + 0], al, bh[0], bh[1]);
            mma16816(S[2 * jp + 0], ah, bl[0], bl[1]);
            mma16816(S[2 * jp + 1], ah, bh[2], bh[3]);
            mma16816(S[2 * jp + 1], al, bh[2], bh[3]);
            mma16816(S[2 * jp + 1], ah, bl[2], bl[3]);
        }
    }
}

// ============================================================================
// Kernel 1: attention compute; attn gets UNNORMALIZED exp(S)
// ============================================================================
__global__ __launch_bounds__(256, 2)
void attn_main_kernel(const float* __restrict__ q, const float* __restrict__ k,
                      const float* __restrict__ v, float* __restrict__ out,
                      float* __restrict__ attn) {
    extern __shared__ char smc[];
    const uint32_t sb = smem_u32(smc);
    float* lsm = (float*)(smc + OFF_L);
    const float* rawk = (const float*)(smc + OFF_RAWK);
    const float* rawv = (const float*)(smc + OFF_RAWV);

    const int tid = threadIdx.x;
    const int lane = tid & 31;
    const int wid = tid >> 5;                 // owns q rows wid*16..+15
    const int g = lane >> 2, t = lane & 3;
    const int wr = wid * 16;

    const int arow = lane & 15, akh = lane >> 4;
    const int brow = ((lane >> 4) & 1) * 8 + (lane & 7), bkh = (lane >> 3) & 1;

    const int qt = (NQT - 1) - blockIdx.x;    // heavy tiles first
    const int bh = blockIdx.y;
    const int b = bh >> 4, h = bh & 15;

    const float* qb = q + (long long)b * kS * kE + h * 64;
    const float* kb = k + (long long)b * kS * kE + h * 64;
    const float* vb = v + (long long)b * kS * kE + h * 64;
    float* ob = out + (long long)b * kS * kE + h * 64;
    float* ab = attn ? attn + (long long)bh * kS * kS : nullptr;

    const int nkt = 2 * qt + 2;               // 64-key tiles
    const int qrow_g = qt * 128 + wr + g;     // rows for c0/c1; +8 for c2/c3

    // per-thread cp.async source/dst indices (4 float4 for K, 4 for V)
    const int cr = tid >> 4;                  // 0..15  (row group)
    const int cd = (tid & 15) << 2;           // 0..60  (col float4 base)

    // ---- prologue: start cp.async for tile 0 ----
    {
        #pragma unroll
        for (int i = 0; i < 4; i++) {
            int r = cr + i * 16;
            cp16(sb + OFF_RAWK + (uint32_t)(r * 64 + cd) * 4, &kb[(long long)r * kE + cd]);
            cp16(sb + OFF_RAWV + (uint32_t)(r * 64 + cd) * 4, &vb[(long long)r * kE + cd]);
        }
        CP_COMMIT();
    }

    // ---- load Q (x 1/8, hi/lo bf16 split) ----
    #pragma unroll
    for (int i = 0; i < 8; i++) {
        int e4 = tid + i * 256;
        int r = e4 >> 4, d4 = (e4 & 15) << 2;
        float4 x = *(const float4*)&qb[(long long)(qt * 128 + r) * kE + d4];
        x.x *= 0.125f; x.y *= 0.125f; x.z *= 0.125f; x.w *= 0.125f;
        float h0 = bfr(x.x), h1 = bfr(x.y), h2 = bfr(x.z), h3 = bfr(x.w);
        uint32_t off = (uint32_t)((r * QSTR + d4) * 2);
        *(uint32_t*)(smc + OFF_QH + off)     = packbf(h0, h1);
        *(uint32_t*)(smc + OFF_QH + off + 4) = packbf(h2, h3);
        *(uint32_t*)(smc + OFF_QL + off)     = packbf(x.x - h0, x.y - h1);
        *(uint32_t*)(smc + OFF_QL + off + 4) = packbf(x.z - h2, x.w - h3);
    }

    float O[8][4];
    #pragma unroll
    for (int nb = 0; nb < 8; nb++)
        #pragma unroll
        for (int c = 0; c < 4; c++) O[nb][c] = 0.0f;
    float lp0 = 0.0f, lp1 = 0.0f;

    for (int kt = 0; kt < nkt; kt++) {
        // ---- wait for raw tile, then convert raw -> bf16 hi/lo buffers ----
        CP_WAIT0();
        __syncthreads();

        // K: [64][64]
        #pragma unroll
        for (int i = 0; i < 4; i++) {
            int e4 = tid + i * 256;
            int r = e4 >> 4, d4 = (e4 & 15) << 2;
            float4 x = *(const float4*)&rawk[r * 64 + d4];
            float h0 = bfr(x.x), h1 = bfr(x.y), h2 = bfr(x.z), h3 = bfr(x.w);
            uint32_t off = (uint32_t)((r * QSTR + d4) * 2);
            *(uint32_t*)(smc + OFF_KH + off)     = packbf(h0, h1);
            *(uint32_t*)(smc + OFF_KH + off + 4) = packbf(h2, h3);
            *(uint32_t*)(smc + OFF_KL + off)     = packbf(x.x - h0, x.y - h1);
            *(uint32_t*)(smc + OFF_KL + off + 4) = packbf(x.z - h2, x.w - h3);
        }
        // V: transpose into Vt[d][key]
        #pragma unroll
        for (int i = 0; i < 4; i++) {
            int idx = tid + i * 256;
            int key = idx >> 4, dg = idx & 15;
            float4 x = *(const float4*)&rawv[key * 64 + dg * 4];
            #pragma unroll
            for (int j = 0; j < 4; j++) {
                float val = (&x.x)[j];
                float hi = bfr(val);
                int d = dg * 4 + j;
                *(__nv_bfloat16*)(smc + OFF_VH + (d * QSTR + key) * 2) = __float2bfloat16(hi);
                *(__nv_bfloat16*)(smc + OFF_VL + (d * QSTR + key) * 2) = __float2bfloat16(val - hi);
            }
        }
        __syncthreads();

        // ---- kick off loads for next tile (overlaps compute below) ----
        if (kt + 1 < nkt) {
            const long long kr0 = (long long)(kt + 1) * 64;
            #pragma unroll
            for (int i = 0; i < 4; i++) {
                int r = cr + i * 16;
                cp16(sb + OFF_RAWK + (uint32_t)(r * 64 + cd) * 4, &kb[(kr0 + r) * kE + cd]);
                cp16(sb + OFF_RAWV + (uint32_t)(r * 64 + cd) * 4, &vb[(kr0 + r) * kE + cd]);
            }
            CP_COMMIT();
        }

        // ---- S = Q*K^T ----
        float S[8][4];
        #pragma unroll
        for (int j = 0; j < 8; j++)
            #pragma unroll
            for (int c = 0; c < 4; c++) S[j][c] = 0.0f;
        s_gemm(S, sb, wr, arow, akh, brow, bkh);

        // ---- epilogue: exp, write unnormalized attn, l-partials, P frags ----
        const bool need_mask = (kt * 64 + 63 > qt * 128 + wr);
        uint32_t ph[8][2], pl[8][2];
        #pragma unroll
        for (int j = 0; j < 8; j++) {
            const int c0 = kt * 64 + j * 8 + 2 * t;
            float e0 = __expf(S[j][0]), e1 = __expf(S[j][1]);
            float e2 = __expf(S[j][2]), e3 = __expf(S[j][3]);
            if (need_mask) {
                if (c0     > qrow_g)     e0 = 0.0f;
                if (c0 + 1 > qrow_g)     e1 = 0.0f;
                if (c0     > qrow_g + 8) e2 = 0.0f;
                if (c0 + 1 > qrow_g + 8) e3 = 0.0f;
            }
            if (ab) {
                *(float2*)&ab[(long long)qrow_g * kS + c0]       = make_float2(e0, e1);
                *(float2*)&ab[(long long)(qrow_g + 8) * kS + c0] = make_float2(e2, e3);
            }
            lp0 += e0 + e1;
            lp1 += e2 + e3;
            float h0 = bfr(e0), h1 = bfr(e1), h2 = bfr(e2), h3 = bfr(e3);
            ph[j][0] = packbf(h0, h1);
            ph[j][1] = packbf(h2, h3);
            pl[j][0] = packbf(e0 - h0, e1 - h1);
            pl[j][1] = packbf(e2 - h2, e3 - h3);
        }

        // ---- O += P*V ----
        #pragma unroll
        for (int kb4 = 0; kb4 < 4; kb4++) {
            uint32_t Ah[4] = {ph[2 * kb4][0], ph[2 * kb4][1],
                              ph[2 * kb4 + 1][0], ph[2 * kb4 + 1][1]};
            uint32_t Al[4] = {pl[2 * kb4][0], pl[2 * kb4][1],
                              pl[2 * kb4 + 1][0], pl[2 * kb4 + 1][1]};
            #pragma unroll
            for (int np = 0; np < 4; np++) {
                uint32_t boff = (uint32_t)(((np * 16 + brow) * QSTR + kb4 * 16 + bkh * 8) * 2);
                uint32_t vh[4], vl[4];
                ldsm4(vh, sb + OFF_VH + boff);
                ldsm4(vl, sb + OFF_VL + boff);
                mma16816(O[2 * np + 0], Ah, vh[0], vh[1]);
                mma16816(O[2 * np + 0], Al, vh[0], vh[1]);
                mma16816(O[2 * np + 0], Ah, vl[0], vl[1]);
                mma16816(O[2 * np + 1], Ah, vh[2], vh[3]);
                mma16816(O[2 * np + 1], Al, vh[2], vh[3]);
                mma16816(O[2 * np + 1], Ah, vl[2], vl[3]);
            }
        }
    }

    // ---- reduce l across quad lanes ----
    lp0 += __shfl_xor_sync(0xffffffffu, lp0, 1);
    lp0 += __shfl_xor_sync(0xffffffffu, lp0, 2);
    lp1 += __shfl_xor_sync(0xffffffffu, lp1, 1);
    lp1 += __shfl_xor_sync(0xffffffffu, lp1, 2);
    __syncthreads();
    if (t == 0) {
        lsm[wr + g] = lp0;
        lsm[wr + 8 + g] = lp1;
    }
    __syncthreads();
    const float ril = 1.0f / lsm[wr + g];
    const float rih = 1.0f / lsm[wr + 8 + g];
    if (t == 0) {
        g_rinv[bh * kS + qrow_g] = ril;
        g_rinv[bh * kS + qrow_g + 8] = rih;
    }

    // ---- write O (normalized) ----
    #pragma unroll
    for (int nb = 0; nb < 8; nb++) {
        const int c0 = nb * 8 + 2 * t;
        *(float2*)&ob[(long long)qrow_g * kE + c0] =
            make_float2(O[nb][0] * ril, O[nb][1] * ril);
        *(float2*)&ob[(long long)(qrow_g + 8) * kE + c0] =
            make_float2(O[nb][2] * rih, O[nb][3] * rih);
    }

    // ---- zero-fill masked columns [nkt*64, 2048) ----
    if (ab) {
        const int cz0 = nkt * 64;
        const int w4 = (kS - cz0) >> 2;
        if (w4 > 0) {
            const float4 z4 = make_float4(0.f, 0.f, 0.f, 0.f);
            for (int i = tid; i < 128 * w4; i += 256) {
                int r = i / w4;
                int c = (i - r * w4) * 4 + cz0;
                *(float4*)&ab[(long long)(qt * 128 + r) * kS + c] = z4;
            }
        }
    }
}

// ============================================================================
// Kernel 2: uniform 128x128-tile scale of the causal region by 1/l
// grid.x = 136 (triangular tile id), grid.y = 32 (bh)
// ============================================================================
__global__ __launch_bounds__(256)
void attn_scale_kernel(float* __restrict__ attn) {
    __shared__ float rsm[128];
    const int tri = blockIdx.x;
    // decode triangular index -> (qt, ct)
    int qt = (int)((sqrtf(8.0f * (float)tri + 1.0f) - 1.0f) * 0.5f);
    while ((qt + 1) * (qt + 2) / 2 <= tri) qt++;
    while (qt * (qt + 1) / 2 > tri) qt--;
    const int ct = tri - qt * (qt + 1) / 2;
    const int bh = blockIdx.y;

    const int tid = threadIdx.x;
    if (tid < 128) rsm[tid] = g_rinv[bh * kS + qt * 128 + tid];
    __syncthreads();

    float4* base = (float4*)(attn + (long long)bh * kS * kS +
                             (long long)(qt * 128) * kS + ct * 128);
    #pragma unroll
    for (int i = 0; i < 16; i++) {
        int idx = tid + i * 256;           // 0..4095
        int row = idx >> 5, c4 = idx & 31;
        float4* p = base + (long long)row * (kS >> 2) + c4;
        float4 x = *p;
        const float s = rsm[row];
        x.x *= s; x.y *= s; x.z *= s; x.w *= s;
        *p = x;
    }
}

extern "C" void kernel_launch(void* const* d_in, const int* in_sizes, int n_in,
                              void* d_out, int out_size) {
    const float* q = (const float*)d_in[0];
    const float* k = (const float*)d_in[1];
    const float* v = (const float*)d_in[2];
    float* out = (float*)d_out;

    float* attn = nullptr;
    if ((long long)out_size >= OUT_ELEMS + ATTN_ELEMS) attn = out + OUT_ELEMS;

    cudaFuncSetAttribute(attn_main_kernel,
                         cudaFuncAttributeMaxDynamicSharedMemorySize, SMEM_BYTES);

    dim3 grid(NQT, 32);
    attn_main_kernel<<<grid, 256, SMEM_BYTES>>>(q, k, v, out, attn);
    if (attn) {
        dim3 sgrid(136, 32);
        attn_scale_kernel<<<sgrid, 256>>>(attn);
    }
}

// round 8
// speedup vs baseline: 1.4227x; 1.3472x over previous
#include <cuda_runtime.h>
#include <cuda_fp16.h>
#include <math.h>
#include <stdint.h>

// ============================================================================
// Causal MHA, sm_103. Kernel 1: FA2-style single pass, mma.sync fp16 with
// asymmetric hi/lo split (Q,P split; K,V single fp16), cp.async pipelined.
// Writes out + UNNORMALIZED exp(S) to attn + per-row 1/l.
// Kernel 2: uniform-tile streaming scale of attn by 1/l.
// ============================================================================

namespace {
constexpr int kS = 2048, kE = 1024;
constexpr int NQT = 16;                          // 128-row q tiles
constexpr long long OUT_ELEMS  = 4194304LL;
constexpr long long ATTN_ELEMS = 134217728LL;

constexpr int QSTR = 72;                         // fp16 elems per row (144B)
constexpr int OFF_QH = 0;                        // Q hi [128][64] fp16
constexpr int OFF_QL = OFF_QH + 128 * QSTR * 2;  // 18432
constexpr int OFF_K  = OFF_QL + 128 * QSTR * 2;  // 36864  K [64][64] fp16
constexpr int OFF_V  = OFF_K + 64 * QSTR * 2;    // 46080  Vt [64 d][64 key] fp16
constexpr int OFF_L  = OFF_V + 64 * QSTR * 2;    // 55296 (512B)
constexpr int OFF_RAWK = 55808;                  // raw K [64][64] f32 (16KB)
constexpr int OFF_RAWV = OFF_RAWK + 16384;       // raw V [64][64] f32 (16KB)
constexpr int SMEM_BYTES = OFF_RAWV + 16384;     // 88576
}  // namespace

__device__ float g_rinv[32 * 2048];              // per (bh,row) 1/l

__device__ __forceinline__ uint32_t smem_u32(const void* p) {
    uint32_t a;
    asm("{ .reg .u64 t; cvta.to.shared.u64 t, %1; cvt.u32.u64 %0, t; }" : "=r"(a) : "l"(p));
    return a;
}
__device__ __forceinline__ void ldsm4(uint32_t r[4], uint32_t addr) {
    asm volatile("ldmatrix.sync.aligned.m8n8.x4.shared.b16 {%0,%1,%2,%3}, [%4];"
                 : "=r"(r[0]), "=r"(r[1]), "=r"(r[2]), "=r"(r[3]) : "r"(addr));
}
__device__ __forceinline__ void mma16816(float c[4], const uint32_t a[4],
                                         uint32_t b0, uint32_t b1) {
    asm("mma.sync.aligned.m16n8k16.row.col.f32.f16.f16.f32 "
        "{%0,%1,%2,%3}, {%4,%5,%6,%7}, {%8,%9}, {%0,%1,%2,%3};"
        : "+f"(c[0]), "+f"(c[1]), "+f"(c[2]), "+f"(c[3])
        : "r"(a[0]), "r"(a[1]), "r"(a[2]), "r"(a[3]), "r"(b0), "r"(b1));
}
__device__ __forceinline__ float hfr(float x) {          // fp16-rounded value
    return __half2float(__float2half_rn(x));
}
__device__ __forceinline__ uint32_t packhf(float lo_c, float hi_c) {  // {low, high}
    uint32_t r;
    asm("cvt.rn.f16x2.f32 %0, %1, %2;" : "=r"(r) : "f"(hi_c), "f"(lo_c));
    return r;
}
__device__ __forceinline__ void cp16(uint32_t smaddr, const void* gaddr) {
    asm volatile("cp.async.cg.shared.global [%0], [%1], 16;"
                 :: "r"(smaddr), "l"(gaddr) : "memory");
}
#define CP_COMMIT() asm volatile("cp.async.commit_group;" ::: "memory")
#define CP_WAIT0()  asm volatile("cp.async.wait_group 0;" ::: "memory")

// S[j][4] += (Qhi+Qlo)(16 rows of this warp) * K16_tile(64x64)^T
__device__ __forceinline__ void s_gemm(float (&S)[8][4], uint32_t sb, int wr,
                                       int arow, int akh, int brow, int bkh) {
    #pragma unroll
    for (int kb = 0; kb < 4; kb++) {
        uint32_t ah[4], al[4];
        uint32_t aoff = (uint32_t)(((wr + arow) * QSTR + kb * 16 + akh * 8) * 2);
        ldsm4(ah, sb + OFF_QH + aoff);
        ldsm4(al, sb + OFF_QL + aoff);
        #pragma unroll
        for (int jp = 0; jp < 4; jp++) {
            uint32_t boff = (uint32_t)(((jp * 16 + brow) * QSTR + kb * 16 + bkh * 8) * 2);
            uint32_t bh[4];
            ldsm4(bh, sb + OFF_K + boff);
            mma16816(S[2 * jp + 0], ah, bh[0], bh[1]);
            mma16816(S[2 * jp + 1], ah, bh[2], bh[3]);
            mma16816(S[2 * jp + 0], al, bh[0], bh[1]);
            mma16816(S[2 * jp + 1], al, bh[2], bh[3]);
        }
    }
}

// ============================================================================
// Kernel 1: attention compute; attn gets UNNORMALIZED exp(S)
// ============================================================================
__global__ __launch_bounds__(256, 2)
void attn_main_kernel(const float* __restrict__ q, const float* __restrict__ k,
                      const float* __restrict__ v, float* __restrict__ out,
                      float* __restrict__ attn) {
    extern __shared__ char smc[];
    const uint32_t sb = smem_u32(smc);
    float* lsm = (float*)(smc + OFF_L);
    const float* rawk = (const float*)(smc + OFF_RAWK);
    const float* rawv = (const float*)(smc + OFF_RAWV);

    const int tid = threadIdx.x;
    const int lane = tid & 31;
    const int wid = tid >> 5;                 // owns q rows wid*16..+15
    const int g = lane >> 2, t = lane & 3;
    const int wr = wid * 16;

    const int arow = lane & 15, akh = lane >> 4;
    const int brow = ((lane >> 4) & 1) * 8 + (lane & 7), bkh = (lane >> 3) & 1;

    const int qt = (NQT - 1) - blockIdx.x;    // heavy tiles first
    const int bh = blockIdx.y;
    const int b = bh >> 4, h = bh & 15;

    const float* qb = q + (long long)b * kS * kE + h * 64;
    const float* kb = k + (long long)b * kS * kE + h * 64;
    const float* vb = v + (long long)b * kS * kE + h * 64;
    float* ob = out + (long long)b * kS * kE + h * 64;
    float* ab = attn ? attn + (long long)bh * kS * kS : nullptr;

    const int nkt = 2 * qt + 2;               // 64-key tiles
    const int qrow_g = qt * 128 + wr + g;     // rows for c0/c1; +8 for c2/c3

    // per-thread cp.async indices (4 float4 for K, 4 for V)
    const int cr = tid >> 4;                  // 0..15
    const int cd = (tid & 15) << 2;           // 0..60

    // ---- prologue: start cp.async for tile 0 ----
    {
        #pragma unroll
        for (int i = 0; i < 4; i++) {
            int r = cr + i * 16;
            cp16(sb + OFF_RAWK + (uint32_t)(r * 64 + cd) * 4, &kb[(long long)r * kE + cd]);
            cp16(sb + OFF_RAWV + (uint32_t)(r * 64 + cd) * 4, &vb[(long long)r * kE + cd]);
        }
        CP_COMMIT();
    }

    // ---- load Q (x 1/8, hi/lo fp16 split) ----
    #pragma unroll
    for (int i = 0; i < 8; i++) {
        int e4 = tid + i * 256;
        int r = e4 >> 4, d4 = (e4 & 15) << 2;
        float4 x = *(const float4*)&qb[(long long)(qt * 128 + r) * kE + d4];
        x.x *= 0.125f; x.y *= 0.125f; x.z *= 0.125f; x.w *= 0.125f;
        float h0 = hfr(x.x), h1 = hfr(x.y), h2 = hfr(x.z), h3 = hfr(x.w);
        uint32_t off = (uint32_t)((r * QSTR + d4) * 2);
        *(uint32_t*)(smc + OFF_QH + off)     = packhf(h0, h1);
        *(uint32_t*)(smc + OFF_QH + off + 4) = packhf(h2, h3);
        *(uint32_t*)(smc + OFF_QL + off)     = packhf(x.x - h0, x.y - h1);
        *(uint32_t*)(smc + OFF_QL + off + 4) = packhf(x.z - h2, x.w - h3);
    }

    float O[8][4];
    #pragma unroll
    for (int nb = 0; nb < 8; nb++)
        #pragma unroll
        for (int c = 0; c < 4; c++) O[nb][c] = 0.0f;
    float lp0 = 0.0f, lp1 = 0.0f;

    for (int kt = 0; kt < nkt; kt++) {
        // ---- wait for raw tile, convert to fp16 buffers ----
        CP_WAIT0();
        __syncthreads();

        // K: [64][64] single fp16
        #pragma unroll
        for (int i = 0; i < 4; i++) {
            int e4 = tid + i * 256;
            int r = e4 >> 4, d4 = (e4 & 15) << 2;
            float4 x = *(const float4*)&rawk[r * 64 + d4];
            uint32_t off = (uint32_t)((r * QSTR + d4) * 2);
            *(uint32_t*)(smc + OFF_K + off)     = packhf(x.x, x.y);
            *(uint32_t*)(smc + OFF_K + off + 4) = packhf(x.z, x.w);
        }
        // V: transpose into Vt[d][key], single fp16
        #pragma unroll
        for (int i = 0; i < 4; i++) {
            int idx = tid + i * 256;
            int key = idx >> 4, dg = idx & 15;
            float4 x = *(const float4*)&rawv[key * 64 + dg * 4];
            #pragma unroll
            for (int j = 0; j < 4; j++) {
                int d = dg * 4 + j;
                *(__half*)(smc + OFF_V + (d * QSTR + key) * 2) = __float2half_rn((&x.x)[j]);
            }
        }
        __syncthreads();

        // ---- kick off loads for next tile (overlaps compute) ----
        if (kt + 1 < nkt) {
            const long long kr0 = (long long)(kt + 1) * 64;
            #pragma unroll
            for (int i = 0; i < 4; i++) {
                int r = cr + i * 16;
                cp16(sb + OFF_RAWK + (uint32_t)(r * 64 + cd) * 4, &kb[(kr0 + r) * kE + cd]);
                cp16(sb + OFF_RAWV + (uint32_t)(r * 64 + cd) * 4, &vb[(kr0 + r) * kE + cd]);
            }
            CP_COMMIT();
        }

        // ---- S = Q*K^T ----
        float S[8][4];
        #pragma unroll
        for (int j = 0; j < 8; j++)
            #pragma unroll
            for (int c = 0; c < 4; c++) S[j][c] = 0.0f;
        s_gemm(S, sb, wr, arow, akh, brow, bkh);

        // ---- epilogue: exp, write unnormalized attn, l-partials, P frags ----
        const bool need_mask = (kt * 64 + 63 > qt * 128 + wr);
        uint32_t ph[8][2], pl[8][2];
        #pragma unroll
        for (int j = 0; j < 8; j++) {
            const int c0 = kt * 64 + j * 8 + 2 * t;
            float e0 = __expf(S[j][0]), e1 = __expf(S[j][1]);
            float e2 = __expf(S[j][2]), e3 = __expf(S[j][3]);
            if (need_mask) {
                if (c0     > qrow_g)     e0 = 0.0f;
                if (c0 + 1 > qrow_g)     e1 = 0.0f;
                if (c0     > qrow_g + 8) e2 = 0.0f;
                if (c0 + 1 > qrow_g + 8) e3 = 0.0f;
            }
            if (ab) {
                *(float2*)&ab[(long long)qrow_g * kS + c0]       = make_float2(e0, e1);
                *(float2*)&ab[(long long)(qrow_g + 8) * kS + c0] = make_float2(e2, e3);
            }
            lp0 += e0 + e1;
            lp1 += e2 + e3;
            float h0 = hfr(e0), h1 = hfr(e1), h2 = hfr(e2), h3 = hfr(e3);
            ph[j][0] = packhf(h0, h1);
            ph[j][1] = packhf(h2, h3);
            pl[j][0] = packhf(e0 - h0, e1 - h1);
            pl[j][1] = packhf(e2 - h2, e3 - h3);
        }

        // ---- O += P*V (A = P hi/lo from regs, B = V16 fragments) ----
        #pragma unroll
        for (int kb4 = 0; kb4 < 4; kb4++) {
            uint32_t Ah[4] = {ph[2 * kb4][0], ph[2 * kb4][1],
                              ph[2 * kb4 + 1][0], ph[2 * kb4 + 1][1]};
            uint32_t Al[4] = {pl[2 * kb4][0], pl[2 * kb4][1],
                              pl[2 * kb4 + 1][0], pl[2 * kb4 + 1][1]};
            #pragma unroll
            for (int np = 0; np < 4; np++) {
                uint32_t boff = (uint32_t)(((np * 16 + brow) * QSTR + kb4 * 16 + bkh * 8) * 2);
                uint32_t vh[4];
                ldsm4(vh, sb + OFF_V + boff);
                mma16816(O[2 * np + 0], Ah, vh[0], vh[1]);
                mma16816(O[2 * np + 1], Ah, vh[2], vh[3]);
                mma16816(O[2 * np + 0], Al, vh[0], vh[1]);
                mma16816(O[2 * np + 1], Al, vh[2], vh[3]);
            }
        }
    }

    // ---- reduce l across quad lanes ----
    lp0 += __shfl_xor_sync(0xffffffffu, lp0, 1);
    lp0 += __shfl_xor_sync(0xffffffffu, lp0, 2);
    lp1 += __shfl_xor_sync(0xffffffffu, lp1, 1);
    lp1 += __shfl_xor_sync(0xffffffffu, lp1, 2);
    __syncthreads();
    if (t == 0) {
        lsm[wr + g] = lp0;
        lsm[wr + 8 + g] = lp1;
    }
    __syncthreads();
    const float ril = 1.0f / lsm[wr + g];
    const float rih = 1.0f / lsm[wr + 8 + g];
    if (t == 0) {
        g_rinv[bh * kS + qrow_g] = ril;
        g_rinv[bh * kS + qrow_g + 8] = rih;
    }

    // ---- write O (normalized) ----
    #pragma unroll
    for (int nb = 0; nb < 8; nb++) {
        const int c0 = nb * 8 + 2 * t;
        *(float2*)&ob[(long long)qrow_g * kE + c0] =
            make_float2(O[nb][0] * ril, O[nb][1] * ril);
        *(float2*)&ob[(long long)(qrow_g + 8) * kE + c0] =
            make_float2(O[nb][2] * rih, O[nb][3] * rih);
    }

    // ---- zero-fill masked columns [nkt*64, 2048) ----
    if (ab) {
        const int cz0 = nkt * 64;
        const int w4 = (kS - cz0) >> 2;
        if (w4 > 0) {
            const float4 z4 = make_float4(0.f, 0.f, 0.f, 0.f);
            for (int i = tid; i < 128 * w4; i += 256) {
                int r = i / w4;
                int c = (i - r * w4) * 4 + cz0;
                *(float4*)&ab[(long long)(qt * 128 + r) * kS + c] = z4;
            }
        }
    }
}

// ============================================================================
// Kernel 2: uniform 128x128-tile scale of the causal region by 1/l
// ============================================================================
__global__ __launch_bounds__(256)
void attn_scale_kernel(float* __restrict__ attn) {
    __shared__ float rsm[128];
    const int tri = blockIdx.x;
    int qt = (int)((sqrtf(8.0f * (float)tri + 1.0f) - 1.0f) * 0.5f);
    while ((qt + 1) * (qt + 2) / 2 <= tri) qt++;
    while (qt * (qt + 1) / 2 > tri) qt--;
    const int ct = tri - qt * (qt + 1) / 2;
    const int bh = blockIdx.y;

    const int tid = threadIdx.x;
    if (tid < 128) rsm[tid] = g_rinv[bh * kS + qt * 128 + tid];
    __syncthreads();

    float4* base = (float4*)(attn + (long long)bh * kS * kS +
                             (long long)(qt * 128) * kS + ct * 128);
    #pragma unroll
    for (int i = 0; i < 16; i++) {
        int idx = tid + i * 256;           // 0..4095
        int row = idx >> 5, c4 = idx & 31;
        float4* p = base + (long long)row * (kS >> 2) + c4;
        float4 x = *p;
        const float s = rsm[row];
        x.x *= s; x.y *= s; x.z *= s; x.w *= s;
        *p = x;
    }
}

extern "C" void kernel_launch(void* const* d_in, const int* in_sizes, int n_in,
                              void* d_out, int out_size) {
    const float* q = (const float*)d_in[0];
    const float* k = (const float*)d_in[1];
    const float* v = (const float*)d_in[2];
    float* out = (float*)d_out;

    float* attn = nullptr;
    if ((long long)out_size >= OUT_ELEMS + ATTN_ELEMS) attn = out + OUT_ELEMS;

    cudaFuncSetAttribute(attn_main_kernel,
                         cudaFuncAttributeMaxDynamicSharedMemorySize, SMEM_BYTES);

    dim3 grid(NQT, 32);
    attn_main_kernel<<<grid, 256, SMEM_BYTES>>>(q, k, v, out, attn);
    if (attn) {
        dim3 sgrid(136, 32);
        attn_scale_kernel<<<sgrid, 256>>>(attn);
    }
}

// round 9
// speedup vs baseline: 1.6937x; 1.1905x over previous
#include <cuda_runtime.h>
#include <cuda_fp16.h>
#include <math.h>
#include <stdint.h>

// ============================================================================
// Causal MHA, sm_103. Kernel 1: FA2-style single pass, mma.sync fp16 with
// asymmetric hi/lo split (Q,P split; K,V single fp16), cp.async pipelined.
// Stages UNNORMALIZED exp(S) as fp16 in a device scratch; writes out + 1/l.
// Kernel 2: reads fp16 stage, writes normalized fp32 attn (causal tiles).
// ============================================================================

namespace {
constexpr int kS = 2048, kE = 1024;
constexpr int NQT = 16;                          // 128-row q tiles
constexpr long long OUT_ELEMS  = 4194304LL;
constexpr long long ATTN_ELEMS = 134217728LL;

constexpr int QSTR = 72;                         // fp16 elems per row (144B)
constexpr int OFF_QH = 0;                        // Q hi [128][64] fp16
constexpr int OFF_QL = OFF_QH + 128 * QSTR * 2;  // 18432
constexpr int OFF_K  = OFF_QL + 128 * QSTR * 2;  // 36864  K [64 key][64 d] fp16
constexpr int OFF_V  = OFF_K + 64 * QSTR * 2;    // 46080  V [64 key][64 d] fp16 (natural)
constexpr int OFF_L  = OFF_V + 64 * QSTR * 2;    // 55296 (512B)
constexpr int OFF_RAWK = 55808;                  // raw K [64][64] f32 (16KB)
constexpr int OFF_RAWV = OFF_RAWK + 16384;       // raw V [64][64] f32 (16KB)
constexpr int SMEM_BYTES = OFF_RAWV + 16384;     // 88576
}  // namespace

__device__ float g_rinv[32 * 2048];              // per (bh,row) 1/l
__device__ __half g_pstage[ATTN_ELEMS];          // unnormalized exp(S), fp16

__device__ __forceinline__ uint32_t smem_u32(const void* p) {
    uint32_t a;
    asm("{ .reg .u64 t; cvta.to.shared.u64 t, %1; cvt.u32.u64 %0, t; }" : "=r"(a) : "l"(p));
    return a;
}
__device__ __forceinline__ void ldsm4(uint32_t r[4], uint32_t addr) {
    asm volatile("ldmatrix.sync.aligned.m8n8.x4.shared.b16 {%0,%1,%2,%3}, [%4];"
                 : "=r"(r[0]), "=r"(r[1]), "=r"(r[2]), "=r"(r[3]) : "r"(addr));
}
__device__ __forceinline__ void ldsm4t(uint32_t r[4], uint32_t addr) {
    asm volatile("ldmatrix.sync.aligned.m8n8.x4.trans.shared.b16 {%0,%1,%2,%3}, [%4];"
                 : "=r"(r[0]), "=r"(r[1]), "=r"(r[2]), "=r"(r[3]) : "r"(addr));
}
__device__ __forceinline__ void mma16816(float c[4], const uint32_t a[4],
                                         uint32_t b0, uint32_t b1) {
    asm("mma.sync.aligned.m16n8k16.row.col.f32.f16.f16.f32 "
        "{%0,%1,%2,%3}, {%4,%5,%6,%7}, {%8,%9}, {%0,%1,%2,%3};"
        : "+f"(c[0]), "+f"(c[1]), "+f"(c[2]), "+f"(c[3])
        : "r"(a[0]), "r"(a[1]), "r"(a[2]), "r"(a[3]), "r"(b0), "r"(b1));
}
__device__ __forceinline__ float hfr(float x) {
    return __half2float(__float2half_rn(x));
}
__device__ __forceinline__ uint32_t packhf(float lo_c, float hi_c) {  // {low, high}
    uint32_t r;
    asm("cvt.rn.f16x2.f32 %0, %1, %2;" : "=r"(r) : "f"(hi_c), "f"(lo_c));
    return r;
}
__device__ __forceinline__ void cp16(uint32_t smaddr, const void* gaddr) {
    asm volatile("cp.async.cg.shared.global [%0], [%1], 16;"
                 :: "r"(smaddr), "l"(gaddr) : "memory");
}
#define CP_COMMIT() asm volatile("cp.async.commit_group;" ::: "memory")
#define CP_WAIT0()  asm volatile("cp.async.wait_group 0;" ::: "memory")

// S[j][4] += (Qhi+Qlo)(16 rows of this warp) * K16_tile(64x64)^T
__device__ __forceinline__ void s_gemm(float (&S)[8][4], uint32_t sb, int wr,
                                       int arow, int akh, int brow, int bkh) {
    #pragma unroll
    for (int kb = 0; kb < 4; kb++) {
        uint32_t ah[4], al[4];
        uint32_t aoff = (uint32_t)(((wr + arow) * QSTR + kb * 16 + akh * 8) * 2);
        ldsm4(ah, sb + OFF_QH + aoff);
        ldsm4(al, sb + OFF_QL + aoff);
        #pragma unroll
        for (int jp = 0; jp < 4; jp++) {
            uint32_t boff = (uint32_t)(((jp * 16 + brow) * QSTR + kb * 16 + bkh * 8) * 2);
            uint32_t bh[4];
            ldsm4(bh, sb + OFF_K + boff);
            mma16816(S[2 * jp + 0], ah, bh[0], bh[1]);
            mma16816(S[2 * jp + 1], ah, bh[2], bh[3]);
            mma16816(S[2 * jp + 0], al, bh[0], bh[1]);
            mma16816(S[2 * jp + 1], al, bh[2], bh[3]);
        }
    }
}

// ============================================================================
// Kernel 1: attention compute; g_pstage gets UNNORMALIZED exp(S) as fp16
// ============================================================================
__global__ __launch_bounds__(256, 2)
void attn_main_kernel(const float* __restrict__ q, const float* __restrict__ k,
                      const float* __restrict__ v, float* __restrict__ out,
                      float* __restrict__ attn) {
    extern __shared__ char smc[];
    const uint32_t sb = smem_u32(smc);
    float* lsm = (float*)(smc + OFF_L);
    const float* rawk = (const float*)(smc + OFF_RAWK);
    const float* rawv = (const float*)(smc + OFF_RAWV);

    const int tid = threadIdx.x;
    const int lane = tid & 31;
    const int wid = tid >> 5;                 // owns q rows wid*16..+15
    const int g = lane >> 2, t = lane & 3;
    const int wr = wid * 16;

    const int arow = lane & 15, akh = lane >> 4;
    const int brow = ((lane >> 4) & 1) * 8 + (lane & 7), bkh = (lane >> 3) & 1;
    // ldmatrix.trans lane params for V natural layout [key][d]
    const int vrow = ((lane >> 3) & 1) * 8 + (lane & 7);
    const int vcol8 = ((lane >> 4) & 1) * 8;

    const int qt = (NQT - 1) - blockIdx.x;    // heavy tiles first
    const int bh = blockIdx.y;
    const int b = bh >> 4, h = bh & 15;

    const float* qb = q + (long long)b * kS * kE + h * 64;
    const float* kb = k + (long long)b * kS * kE + h * 64;
    const float* vb = v + (long long)b * kS * kE + h * 64;
    float* ob = out + (long long)b * kS * kE + h * 64;
    float* ab = attn ? attn + (long long)bh * kS * kS : nullptr;
    __half* pb = g_pstage + (long long)bh * kS * kS;

    const int nkt = 2 * qt + 2;               // 64-key tiles
    const int qrow_g = qt * 128 + wr + g;     // rows for c0/c1; +8 for c2/c3

    // per-thread cp.async indices (4 float4 for K, 4 for V)
    const int cr = tid >> 4;                  // 0..15
    const int cd = (tid & 15) << 2;           // 0..60

    // ---- prologue: start cp.async for tile 0 ----
    {
        #pragma unroll
        for (int i = 0; i < 4; i++) {
            int r = cr + i * 16;
            cp16(sb + OFF_RAWK + (uint32_t)(r * 64 + cd) * 4, &kb[(long long)r * kE + cd]);
            cp16(sb + OFF_RAWV + (uint32_t)(r * 64 + cd) * 4, &vb[(long long)r * kE + cd]);
        }
        CP_COMMIT();
    }

    // ---- load Q (x 1/8, hi/lo fp16 split) ----
    #pragma unroll
    for (int i = 0; i < 8; i++) {
        int e4 = tid + i * 256;
        int r = e4 >> 4, d4 = (e4 & 15) << 2;
        float4 x = *(const float4*)&qb[(long long)(qt * 128 + r) * kE + d4];
        x.x *= 0.125f; x.y *= 0.125f; x.z *= 0.125f; x.w *= 0.125f;
        float h0 = hfr(x.x), h1 = hfr(x.y), h2 = hfr(x.z), h3 = hfr(x.w);
        uint32_t off = (uint32_t)((r * QSTR + d4) * 2);
        *(uint32_t*)(smc + OFF_QH + off)     = packhf(h0, h1);
        *(uint32_t*)(smc + OFF_QH + off + 4) = packhf(h2, h3);
        *(uint32_t*)(smc + OFF_QL + off)     = packhf(x.x - h0, x.y - h1);
        *(uint32_t*)(smc + OFF_QL + off + 4) = packhf(x.z - h2, x.w - h3);
    }

    float O[8][4];
    #pragma unroll
    for (int nb = 0; nb < 8; nb++)
        #pragma unroll
        for (int c = 0; c < 4; c++) O[nb][c] = 0.0f;
    float lp0 = 0.0f, lp1 = 0.0f;

    for (int kt = 0; kt < nkt; kt++) {
        // ---- wait for raw tile, convert to fp16 buffers ----
        CP_WAIT0();
        __syncthreads();

        // K and V: both natural [key/row][64], packed fp16 stores
        #pragma unroll
        for (int i = 0; i < 4; i++) {
            int e4 = tid + i * 256;
            int r = e4 >> 4, d4 = (e4 & 15) << 2;
            uint32_t off = (uint32_t)((r * QSTR + d4) * 2);
            float4 x = *(const float4*)&rawk[r * 64 + d4];
            *(uint32_t*)(smc + OFF_K + off)     = packhf(x.x, x.y);
            *(uint32_t*)(smc + OFF_K + off + 4) = packhf(x.z, x.w);
            float4 y = *(const float4*)&rawv[r * 64 + d4];
            *(uint32_t*)(smc + OFF_V + off)     = packhf(y.x, y.y);
            *(uint32_t*)(smc + OFF_V + off + 4) = packhf(y.z, y.w);
        }
        __syncthreads();

        // ---- kick off loads for next tile (overlaps compute) ----
        if (kt + 1 < nkt) {
            const long long kr0 = (long long)(kt + 1) * 64;
            #pragma unroll
            for (int i = 0; i < 4; i++) {
                int r = cr + i * 16;
                cp16(sb + OFF_RAWK + (uint32_t)(r * 64 + cd) * 4, &kb[(kr0 + r) * kE + cd]);
                cp16(sb + OFF_RAWV + (uint32_t)(r * 64 + cd) * 4, &vb[(kr0 + r) * kE + cd]);
            }
            CP_COMMIT();
        }

        // ---- S = Q*K^T ----
        float S[8][4];
        #pragma unroll
        for (int j = 0; j < 8; j++)
            #pragma unroll
            for (int c = 0; c < 4; c++) S[j][c] = 0.0f;
        s_gemm(S, sb, wr, arow, akh, brow, bkh);

        // ---- epilogue: exp, stage fp16 attn, l-partials, P frags ----
        const bool need_mask = (kt * 64 + 63 > qt * 128 + wr);
        uint32_t ph[8][2], pl[8][2];
        #pragma unroll
        for (int j = 0; j < 8; j++) {
            const int c0 = kt * 64 + j * 8 + 2 * t;
            float e0 = __expf(S[j][0]), e1 = __expf(S[j][1]);
            float e2 = __expf(S[j][2]), e3 = __expf(S[j][3]);
            if (need_mask) {
                if (c0     > qrow_g)     e0 = 0.0f;
                if (c0 + 1 > qrow_g)     e1 = 0.0f;
                if (c0     > qrow_g + 8) e2 = 0.0f;
                if (c0 + 1 > qrow_g + 8) e3 = 0.0f;
            }
            lp0 += e0 + e1;
            lp1 += e2 + e3;
            float h0 = hfr(e0), h1 = hfr(e1), h2 = hfr(e2), h3 = hfr(e3);
            uint32_t p01 = packhf(h0, h1);
            uint32_t p23 = packhf(h2, h3);
            *(uint32_t*)&pb[(long long)qrow_g * kS + c0]       = p01;
            *(uint32_t*)&pb[(long long)(qrow_g + 8) * kS + c0] = p23;
            ph[j][0] = p01;
            ph[j][1] = p23;
            pl[j][0] = packhf(e0 - h0, e1 - h1);
            pl[j][1] = packhf(e2 - h2, e3 - h3);
        }

        // ---- O += P*V (A = P hi/lo from regs, B via ldmatrix.trans on V) ----
        #pragma unroll
        for (int kb4 = 0; kb4 < 4; kb4++) {
            uint32_t Ah[4] = {ph[2 * kb4][0], ph[2 * kb4][1],
                              ph[2 * kb4 + 1][0], ph[2 * kb4 + 1][1]};
            uint32_t Al[4] = {pl[2 * kb4][0], pl[2 * kb4][1],
                              pl[2 * kb4 + 1][0], pl[2 * kb4 + 1][1]};
            #pragma unroll
            for (int np = 0; np < 4; np++) {
                uint32_t boff = (uint32_t)(((kb4 * 16 + vrow) * QSTR + np * 16 + vcol8) * 2);
                uint32_t vh[4];
                ldsm4t(vh, sb + OFF_V + boff);
                mma16816(O[2 * np + 0], Ah, vh[0], vh[1]);
                mma16816(O[2 * np + 1], Ah, vh[2], vh[3]);
                mma16816(O[2 * np + 0], Al, vh[0], vh[1]);
                mma16816(O[2 * np + 1], Al, vh[2], vh[3]);
            }
        }
    }

    // ---- reduce l across quad lanes ----
    lp0 += __shfl_xor_sync(0xffffffffu, lp0, 1);
    lp0 += __shfl_xor_sync(0xffffffffu, lp0, 2);
    lp1 += __shfl_xor_sync(0xffffffffu, lp1, 1);
    lp1 += __shfl_xor_sync(0xffffffffu, lp1, 2);
    __syncthreads();
    if (t == 0) {
        lsm[wr + g] = lp0;
        lsm[wr + 8 + g] = lp1;
    }
    __syncthreads();
    const float ril = 1.0f / lsm[wr + g];
    const float rih = 1.0f / lsm[wr + 8 + g];
    if (t == 0) {
        g_rinv[bh * kS + qrow_g] = ril;
        g_rinv[bh * kS + qrow_g + 8] = rih;
    }

    // ---- write O (normalized) ----
    #pragma unroll
    for (int nb = 0; nb < 8; nb++) {
        const int c0 = nb * 8 + 2 * t;
        *(float2*)&ob[(long long)qrow_g * kE + c0] =
            make_float2(O[nb][0] * ril, O[nb][1] * ril);
        *(float2*)&ob[(long long)(qrow_g + 8) * kE + c0] =
            make_float2(O[nb][2] * rih, O[nb][3] * rih);
    }

    // ---- zero-fill masked columns [nkt*64, 2048) in fp32 attn ----
    if (ab) {
        const int cz0 = nkt * 64;
        const int w4 = (kS - cz0) >> 2;
        if (w4 > 0) {
            const float4 z4 = make_float4(0.f, 0.f, 0.f, 0.f);
            for (int i = tid; i < 128 * w4; i += 256) {
                int r = i / w4;
                int c = (i - r * w4) * 4 + cz0;
                *(float4*)&ab[(long long)(qt * 128 + r) * kS + c] = z4;
            }
        }
    }
}

// ============================================================================
// Kernel 2: attn[causal tile] = fp16 stage * 1/l  (fp16 read, fp32 write)
// ============================================================================
__global__ __launch_bounds__(256)
void attn_scale_kernel(float* __restrict__ attn) {
    __shared__ float rsm[128];
    const int tri = blockIdx.x;
    int qt = (int)((sqrtf(8.0f * (float)tri + 1.0f) - 1.0f) * 0.5f);
    while ((qt + 1) * (qt + 2) / 2 <= tri) qt++;
    while (qt * (qt + 1) / 2 > tri) qt--;
    const int ct = tri - qt * (qt + 1) / 2;
    const int bh = blockIdx.y;

    const int tid = threadIdx.x;
    if (tid < 128) rsm[tid] = g_rinv[bh * kS + qt * 128 + tid];
    __syncthreads();

    const long long base = (long long)bh * kS * kS + (long long)(qt * 128) * kS + ct * 128;
    const __half* pst = g_pstage + base;
    float* dst = attn + base;

    #pragma unroll
    for (int i = 0; i < 16; i++) {
        int idx = tid + i * 256;           // 0..4095 (float4 units, 32 per row)
        int row = idx >> 5, c4 = idx & 31;
        const float s = rsm[row];
        uint2 hp = *(const uint2*)(pst + (long long)row * kS + c4 * 4);
        float2 f01 = __half22float2(*(const __half2*)&hp.x);
        float2 f23 = __half22float2(*(const __half2*)&hp.y);
        float4 o;
        o.x = f01.x * s; o.y = f01.y * s;
        o.z = f23.x * s; o.w = f23.y * s;
        *(float4*)(dst + (long long)row * kS + c4 * 4) = o;
    }
}

extern "C" void kernel_launch(void* const* d_in, const int* in_sizes, int n_in,
                              void* d_out, int out_size) {
    const float* q = (const float*)d_in[0];
    const float* k = (const float*)d_in[1];
    const float* v = (const float*)d_in[2];
    float* out = (float*)d_out;

    float* attn = nullptr;
    if ((long long)out_size >= OUT_ELEMS + ATTN_ELEMS) attn = out + OUT_ELEMS;

    cudaFuncSetAttribute(attn_main_kernel,
                         cudaFuncAttributeMaxDynamicSharedMemorySize, SMEM_BYTES);

    dim3 grid(NQT, 32);
    attn_main_kernel<<<grid, 256, SMEM_BYTES>>>(q, k, v, out, attn);
    if (attn) {
        dim3 sgrid(136, 32);
        attn_scale_kernel<<<sgrid, 256>>>(attn);
    }
}

// round 10
// speedup vs baseline: 1.9362x; 1.1432x over previous
#include <cuda_runtime.h>
#include <cuda_fp16.h>
#include <math.h>
#include <stdint.h>

// ============================================================================
// Causal MHA, sm_103. Kernel 1: FA2-style single pass, plain fp16 mma.sync,
// cp.async pipelined. Stages UNNORMALIZED exp(S) as fp16 in device scratch;
// writes out + 1/l. Kernel 2: reads fp16 stage, writes normalized fp32 attn.
// ============================================================================

namespace {
constexpr int kS = 2048, kE = 1024;
constexpr int NQT = 16;                          // 128-row q tiles
constexpr long long OUT_ELEMS  = 4194304LL;
constexpr long long ATTN_ELEMS = 134217728LL;

constexpr int QSTR = 72;                         // fp16 elems per row (144B)
constexpr int OFF_Q  = 0;                        // Q [128][64] fp16
constexpr int OFF_K  = OFF_Q + 128 * QSTR * 2;   // 18432  K [64 key][64 d] fp16
constexpr int OFF_V  = OFF_K + 64 * QSTR * 2;    // 27648  V [64 key][64 d] fp16
constexpr int OFF_L  = OFF_V + 64 * QSTR * 2;    // 36864 (512B)
constexpr int OFF_RAWK = 37376;                  // raw K [64][64] f32 (16KB)
constexpr int OFF_RAWV = OFF_RAWK + 16384;       // raw V [64][64] f32 (16KB)
constexpr int SMEM_BYTES = OFF_RAWV + 16384;     // 70144
}  // namespace

__device__ float g_rinv[32 * 2048];              // per (bh,row) 1/l
__device__ __half g_pstage[ATTN_ELEMS];          // unnormalized exp(S), fp16

__device__ __forceinline__ uint32_t smem_u32(const void* p) {
    uint32_t a;
    asm("{ .reg .u64 t; cvta.to.shared.u64 t, %1; cvt.u32.u64 %0, t; }" : "=r"(a) : "l"(p));
    return a;
}
__device__ __forceinline__ void ldsm4(uint32_t r[4], uint32_t addr) {
    asm volatile("ldmatrix.sync.aligned.m8n8.x4.shared.b16 {%0,%1,%2,%3}, [%4];"
                 : "=r"(r[0]), "=r"(r[1]), "=r"(r[2]), "=r"(r[3]) : "r"(addr));
}
__device__ __forceinline__ void ldsm4t(uint32_t r[4], uint32_t addr) {
    asm volatile("ldmatrix.sync.aligned.m8n8.x4.trans.shared.b16 {%0,%1,%2,%3}, [%4];"
                 : "=r"(r[0]), "=r"(r[1]), "=r"(r[2]), "=r"(r[3]) : "r"(addr));
}
__device__ __forceinline__ void mma16816(float c[4], const uint32_t a[4],
                                         uint32_t b0, uint32_t b1) {
    asm("mma.sync.aligned.m16n8k16.row.col.f32.f16.f16.f32 "
        "{%0,%1,%2,%3}, {%4,%5,%6,%7}, {%8,%9}, {%0,%1,%2,%3};"
        : "+f"(c[0]), "+f"(c[1]), "+f"(c[2]), "+f"(c[3])
        : "r"(a[0]), "r"(a[1]), "r"(a[2]), "r"(a[3]), "r"(b0), "r"(b1));
}
__device__ __forceinline__ uint32_t packhf(float lo_c, float hi_c) {  // {low, high}
    uint32_t r;
    asm("cvt.rn.f16x2.f32 %0, %1, %2;" : "=r"(r) : "f"(hi_c), "f"(lo_c));
    return r;
}
__device__ __forceinline__ void cp16(uint32_t smaddr, const void* gaddr) {
    asm volatile("cp.async.cg.shared.global [%0], [%1], 16;"
                 :: "r"(smaddr), "l"(gaddr) : "memory");
}
#define CP_COMMIT() asm volatile("cp.async.commit_group;" ::: "memory")
#define CP_WAIT0()  asm volatile("cp.async.wait_group 0;" ::: "memory")

// S[j][4] += Q16(16 rows of this warp) * K16_tile(64x64)^T
__device__ __forceinline__ void s_gemm(float (&S)[8][4], uint32_t sb, int wr,
                                       int arow, int akh, int brow, int bkh) {
    #pragma unroll
    for (int kb = 0; kb < 4; kb++) {
        uint32_t ah[4];
        uint32_t aoff = (uint32_t)(((wr + arow) * QSTR + kb * 16 + akh * 8) * 2);
        ldsm4(ah, sb + OFF_Q + aoff);
        #pragma unroll
        for (int jp = 0; jp < 4; jp++) {
            uint32_t boff = (uint32_t)(((jp * 16 + brow) * QSTR + kb * 16 + bkh * 8) * 2);
            uint32_t bh[4];
            ldsm4(bh, sb + OFF_K + boff);
            mma16816(S[2 * jp + 0], ah, bh[0], bh[1]);
            mma16816(S[2 * jp + 1], ah, bh[2], bh[3]);
        }
    }
}

// ============================================================================
// Kernel 1: attention compute; g_pstage gets UNNORMALIZED exp(S) as fp16
// ============================================================================
__global__ __launch_bounds__(256, 2)
void attn_main_kernel(const float* __restrict__ q, const float* __restrict__ k,
                      const float* __restrict__ v, float* __restrict__ out,
                      float* __restrict__ attn) {
    extern __shared__ char smc[];
    const uint32_t sb = smem_u32(smc);
    float* lsm = (float*)(smc + OFF_L);
    const float* rawk = (const float*)(smc + OFF_RAWK);
    const float* rawv = (const float*)(smc + OFF_RAWV);

    const int tid = threadIdx.x;
    const int lane = tid & 31;
    const int wid = tid >> 5;                 // owns q rows wid*16..+15
    const int g = lane >> 2, t = lane & 3;
    const int wr = wid * 16;

    const int arow = lane & 15, akh = lane >> 4;
    const int brow = ((lane >> 4) & 1) * 8 + (lane & 7), bkh = (lane >> 3) & 1;
    // ldmatrix.trans lane params for V natural layout [key][d]
    const int vrow = ((lane >> 3) & 1) * 8 + (lane & 7);
    const int vcol8 = ((lane >> 4) & 1) * 8;

    const int qt = (NQT - 1) - blockIdx.x;    // heavy tiles first
    const int bh = blockIdx.y;
    const int b = bh >> 4, h = bh & 15;

    const float* qb = q + (long long)b * kS * kE + h * 64;
    const float* kb = k + (long long)b * kS * kE + h * 64;
    const float* vb = v + (long long)b * kS * kE + h * 64;
    float* ob = out + (long long)b * kS * kE + h * 64;
    float* ab = attn ? attn + (long long)bh * kS * kS : nullptr;
    __half* pb = g_pstage + (long long)bh * kS * kS;

    const int nkt = 2 * qt + 2;               // 64-key tiles
    const int qrow_g = qt * 128 + wr + g;     // rows for c0/c1; +8 for c2/c3

    // per-thread cp.async indices (4 float4 for K, 4 for V)
    const int cr = tid >> 4;                  // 0..15
    const int cd = (tid & 15) << 2;           // 0..60

    // ---- prologue: start cp.async for tile 0 ----
    {
        #pragma unroll
        for (int i = 0; i < 4; i++) {
            int r = cr + i * 16;
            cp16(sb + OFF_RAWK + (uint32_t)(r * 64 + cd) * 4, &kb[(long long)r * kE + cd]);
            cp16(sb + OFF_RAWV + (uint32_t)(r * 64 + cd) * 4, &vb[(long long)r * kE + cd]);
        }
        CP_COMMIT();
    }

    // ---- load Q (x 1/8, single fp16) ----
    #pragma unroll
    for (int i = 0; i < 8; i++) {
        int e4 = tid + i * 256;
        int r = e4 >> 4, d4 = (e4 & 15) << 2;
        float4 x = *(const float4*)&qb[(long long)(qt * 128 + r) * kE + d4];
        uint32_t off = (uint32_t)((r * QSTR + d4) * 2);
        *(uint32_t*)(smc + OFF_Q + off)     = packhf(x.x * 0.125f, x.y * 0.125f);
        *(uint32_t*)(smc + OFF_Q + off + 4) = packhf(x.z * 0.125f, x.w * 0.125f);
    }

    float O[8][4];
    #pragma unroll
    for (int nb = 0; nb < 8; nb++)
        #pragma unroll
        for (int c = 0; c < 4; c++) O[nb][c] = 0.0f;
    float lp0 = 0.0f, lp1 = 0.0f;

    for (int kt = 0; kt < nkt; kt++) {
        // ---- wait for raw tile, convert to fp16 buffers ----
        CP_WAIT0();
        __syncthreads();

        #pragma unroll
        for (int i = 0; i < 4; i++) {
            int e4 = tid + i * 256;
            int r = e4 >> 4, d4 = (e4 & 15) << 2;
            uint32_t off = (uint32_t)((r * QSTR + d4) * 2);
            float4 x = *(const float4*)&rawk[r * 64 + d4];
            *(uint32_t*)(smc + OFF_K + off)     = packhf(x.x, x.y);
            *(uint32_t*)(smc + OFF_K + off + 4) = packhf(x.z, x.w);
            float4 y = *(const float4*)&rawv[r * 64 + d4];
            *(uint32_t*)(smc + OFF_V + off)     = packhf(y.x, y.y);
            *(uint32_t*)(smc + OFF_V + off + 4) = packhf(y.z, y.w);
        }
        __syncthreads();

        // ---- kick off loads for next tile (overlaps compute) ----
        if (kt + 1 < nkt) {
            const long long kr0 = (long long)(kt + 1) * 64;
            #pragma unroll
            for (int i = 0; i < 4; i++) {
                int r = cr + i * 16;
                cp16(sb + OFF_RAWK + (uint32_t)(r * 64 + cd) * 4, &kb[(kr0 + r) * kE + cd]);
                cp16(sb + OFF_RAWV + (uint32_t)(r * 64 + cd) * 4, &vb[(kr0 + r) * kE + cd]);
            }
            CP_COMMIT();
        }

        // ---- S = Q*K^T ----
        float S[8][4];
        #pragma unroll
        for (int j = 0; j < 8; j++)
            #pragma unroll
            for (int c = 0; c < 4; c++) S[j][c] = 0.0f;
        s_gemm(S, sb, wr, arow, akh, brow, bkh);

        // ---- epilogue: exp, stage fp16 attn, l-partials, P frags ----
        const bool need_mask = (kt * 64 + 63 > qt * 128 + wr);
        uint32_t ph[8][2];
        #pragma unroll
        for (int j = 0; j < 8; j++) {
            const int c0 = kt * 64 + j * 8 + 2 * t;
            float e0 = __expf(S[j][0]), e1 = __expf(S[j][1]);
            float e2 = __expf(S[j][2]), e3 = __expf(S[j][3]);
            if (need_mask) {
                if (c0     > qrow_g)     e0 = 0.0f;
                if (c0 + 1 > qrow_g)     e1 = 0.0f;
                if (c0     > qrow_g + 8) e2 = 0.0f;
                if (c0 + 1 > qrow_g + 8) e3 = 0.0f;
            }
            lp0 += e0 + e1;
            lp1 += e2 + e3;
            uint32_t p01 = packhf(e0, e1);
            uint32_t p23 = packhf(e2, e3);
            *(uint32_t*)&pb[(long long)qrow_g * kS + c0]       = p01;
            *(uint32_t*)&pb[(long long)(qrow_g + 8) * kS + c0] = p23;
            ph[j][0] = p01;
            ph[j][1] = p23;
        }

        // ---- O += P*V (A = P fp16 from regs, B via ldmatrix.trans on V) ----
        #pragma unroll
        for (int kb4 = 0; kb4 < 4; kb4++) {
            uint32_t Ah[4] = {ph[2 * kb4][0], ph[2 * kb4][1],
                              ph[2 * kb4 + 1][0], ph[2 * kb4 + 1][1]};
            #pragma unroll
            for (int np = 0; np < 4; np++) {
                uint32_t boff = (uint32_t)(((kb4 * 16 + vrow) * QSTR + np * 16 + vcol8) * 2);
                uint32_t vh[4];
                ldsm4t(vh, sb + OFF_V + boff);
                mma16816(O[2 * np + 0], Ah, vh[0], vh[1]);
                mma16816(O[2 * np + 1], Ah, vh[2], vh[3]);
            }
        }
    }

    // ---- reduce l across quad lanes ----
    lp0 += __shfl_xor_sync(0xffffffffu, lp0, 1);
    lp0 += __shfl_xor_sync(0xffffffffu, lp0, 2);
    lp1 += __shfl_xor_sync(0xffffffffu, lp1, 1);
    lp1 += __shfl_xor_sync(0xffffffffu, lp1, 2);
    __syncthreads();
    if (t == 0) {
        lsm[wr + g] = lp0;
        lsm[wr + 8 + g] = lp1;
    }
    __syncthreads();
    const float ril = 1.0f / lsm[wr + g];
    const float rih = 1.0f / lsm[wr + 8 + g];
    if (t == 0) {
        g_rinv[bh * kS + qrow_g] = ril;
        g_rinv[bh * kS + qrow_g + 8] = rih;
    }

    // ---- write O (normalized) ----
    #pragma unroll
    for (int nb = 0; nb < 8; nb++) {
        const int c0 = nb * 8 + 2 * t;
        *(float2*)&ob[(long long)qrow_g * kE + c0] =
            make_float2(O[nb][0] * ril, O[nb][1] * ril);
        *(float2*)&ob[(long long)(qrow_g + 8) * kE + c0] =
            make_float2(O[nb][2] * rih, O[nb][3] * rih);
    }

    // ---- zero-fill masked columns [nkt*64, 2048) in fp32 attn ----
    if (ab) {
        const int cz0 = nkt * 64;
        const int w4 = (kS - cz0) >> 2;
        if (w4 > 0) {
            const float4 z4 = make_float4(0.f, 0.f, 0.f, 0.f);
            for (int i = tid; i < 128 * w4; i += 256) {
                int r = i / w4;
                int c = (i - r * w4) * 4 + cz0;
                *(float4*)&ab[(long long)(qt * 128 + r) * kS + c] = z4;
            }
        }
    }
}

// ============================================================================
// Kernel 2: attn[causal tile] = fp16 stage * 1/l  (uint4 fp16 read, fp32 write)
// ============================================================================
__global__ __launch_bounds__(256)
void attn_scale_kernel(float* __restrict__ attn) {
    __shared__ float rsm[128];
    const int tri = blockIdx.x;
    int qt = (int)((sqrtf(8.0f * (float)tri + 1.0f) - 1.0f) * 0.5f);
    while ((qt + 1) * (qt + 2) / 2 <= tri) qt++;
    while (qt * (qt + 1) / 2 > tri) qt--;
    const int ct = tri - qt * (qt + 1) / 2;
    const int bh = blockIdx.y;

    const int tid = threadIdx.x;
    if (tid < 128) rsm[tid] = g_rinv[bh * kS + qt * 128 + tid];
    __syncthreads();

    const long long base = (long long)bh * kS * kS + (long long)(qt * 128) * kS + ct * 128;
    const __half* pst = g_pstage + base;
    float* dst = attn + base;

    #pragma unroll
    for (int i = 0; i < 8; i++) {
        int idx = tid + i * 256;           // 0..2047 (8-elem units, 16 per row)
        int row = idx >> 4, c8 = idx & 15;
        const float s = rsm[row];
        uint4 hp = *(const uint4*)(pst + (long long)row * kS + c8 * 8);
        float2 f01 = __half22float2(*(const __half2*)&hp.x);
        float2 f23 = __half22float2(*(const __half2*)&hp.y);
        float2 f45 = __half22float2(*(const __half2*)&hp.z);
        float2 f67 = __half22float2(*(const __half2*)&hp.w);
        float4 o0, o1;
        o0.x = f01.x * s; o0.y = f01.y * s; o0.z = f23.x * s; o0.w = f23.y * s;
        o1.x = f45.x * s; o1.y = f45.y * s; o1.z = f67.x * s; o1.w = f67.y * s;
        float* dp = dst + (long long)row * kS + c8 * 8;
        *(float4*)dp = o0;
        *(float4*)(dp + 4) = o1;
    }
}

extern "C" void kernel_launch(void* const* d_in, const int* in_sizes, int n_in,
                              void* d_out, int out_size) {
    const float* q = (const float*)d_in[0];
    const float* k = (const float*)d_in[1];
    const float* v = (const float*)d_in[2];
    float* out = (float*)d_out;

    float* attn = nullptr;
    if ((long long)out_size >= OUT_ELEMS + ATTN_ELEMS) attn = out + OUT_ELEMS;

    cudaFuncSetAttribute(attn_main_kernel,
                         cudaFuncAttributeMaxDynamicSharedMemorySize, SMEM_BYTES);

    dim3 grid(NQT, 32);
    attn_main_kernel<<<grid, 256, SMEM_BYTES>>>(q, k, v, out, attn);
    if (attn) {
        dim3 sgrid(136, 32);
        attn_scale_kernel<<<sgrid, 256>>>(attn);
    }
}